// round 5
// baseline (speedup 1.0000x reference)
#include <cuda_runtime.h>
#include <math.h>

#define TDIM 1024
#define CDIM 768
#define PH 32
#define PW 32
#define NHEAD 12
#define HS 64
#define NR (8*1024)

__device__ float g_xx [NR*CDIM];
__device__ float g_xxx[NR*CDIM];
__device__ float g_t  [NR*160];
__device__ float g_xw [NR*CDIM];
__device__ float g_xk [NR*CDIM];
__device__ float g_xv [NR*CDIM];
__device__ float g_xr [NR*CDIM];
__device__ float g_xg [NR*CDIM];
__device__ float g_r  [NR*CDIM];
__device__ float g_k  [NR*CDIM];
__device__ float g_v  [NR*CDIM];
__device__ float g_g  [NR*CDIM];
__device__ float g_h1 [NR*64];
__device__ float g_w  [NR*CDIM];
__device__ float g_y  [NR*CDIM];
__device__ float g_yg [NR*CDIM];
__device__ float g_Wc [5*CDIM*CDIM];   // tf32-rounded weights

__device__ __forceinline__ float tf32r(float x) {
    unsigned u;
    asm("cvt.rna.tf32.f32 %0, %1;" : "=r"(u) : "f"(x));
    return __uint_as_float(u);
}

__device__ __forceinline__ void cp16(void* dst, const void* src) {
    unsigned d = (unsigned)__cvta_generic_to_shared(dst);
    asm volatile("cp.async.cg.shared.global [%0], [%1], 16;" :: "r"(d), "l"(src) : "memory");
}

// ---------------- K0: round 5 weight matrices to tf32 ----------------
__global__ void round_w_kernel(const float* __restrict__ w0, const float* __restrict__ w1,
                               const float* __restrict__ w2, const float* __restrict__ w3,
                               const float* __restrict__ w4, float* __restrict__ out)
{
    int idx = blockIdx.x * blockDim.x + threadIdx.x;
    const int NW = CDIM * CDIM;
    if (idx >= 5 * NW) return;
    int m = idx / NW, r = idx % NW;
    const float* src = (m == 0) ? w0 : (m == 1) ? w1 : (m == 2) ? w2 : (m == 3) ? w3 : w4;
    out[idx] = tf32r(src[r]);
}

// ---------------- K1: q_shift + maa_x mix ----------------
__global__ void shift_mix_kernel(const float* __restrict__ x,
                                 const float* __restrict__ maa_x,
                                 float* __restrict__ xx, float* __restrict__ xxx,
                                 int total)
{
    int idx = blockIdx.x * blockDim.x + threadIdx.x;
    if (idx >= total) return;
    int c = idx % CDIM;
    int t = (idx / CDIM) % TDIM;
    int b = idx / (CDIM * TDIM);
    int d  = c & (HS - 1);
    int hh = t >> 5, ww = t & 31;
    float sh = 0.f;
    int st = -1;
    if (d < 16)      { if (ww >= 1)      st = t - 1;  }
    else if (d < 32) { if (ww < PW - 1)  st = t + 1;  }
    else if (d < 48) { if (hh >= 1)      st = t - PW; }
    else             { if (hh < PH - 1)  st = t + PW; }
    if (st >= 0) sh = x[((size_t)b * TDIM + st) * CDIM + c];
    float xv = x[idx];
    float dd = sh - xv;
    xx[idx]  = dd;
    xxx[idx] = xv + dd * maa_x[c];
}

// ---------------- fp32 GEMM (LoRA paths only) ----------------
template<int EPI>
__device__ __forceinline__ float epi_f(float a, const float* bias, int n) {
    if (EPI == 1) return tanhf(a);
    if (EPI == 2) return fmaxf(a, 0.f);
    if (EPI == 3) return a + bias[n];
    return a;
}

template<int EPI, bool BT>
__global__ __launch_bounds__(256, 2) void gemm_kernel(
    const float* __restrict__ A, int lda,
    const float* __restrict__ Bm,
    float* __restrict__ Cm, int ldc,
    int N, int K, const float* __restrict__ bias)
{
    __shared__ __align__(16) float As[16][128];
    __shared__ __align__(16) float Bs[16][132];
    int tid = threadIdx.x;
    int m0 = blockIdx.y * 128, n0 = blockIdx.x * 128;
    int tx = tid & 15, ty = tid >> 4;

    float acc[8][8];
#pragma unroll
    for (int i = 0; i < 8; i++)
#pragma unroll
        for (int j = 0; j < 8; j++) acc[i][j] = 0.f;

    for (int k0 = 0; k0 < K; k0 += 16) {
#pragma unroll
        for (int p = 0; p < 2; p++) {
            int idx = tid + p * 256;
            int r = idx >> 2, kk = (idx & 3) << 2;
            const float4 v = *(const float4*)(A + (size_t)(m0 + r) * lda + k0 + kk);
            As[kk + 0][r] = v.x; As[kk + 1][r] = v.y;
            As[kk + 2][r] = v.z; As[kk + 3][r] = v.w;
        }
        if (BT) {
#pragma unroll
            for (int p = 0; p < 2; p++) {
                int idx = tid + p * 256;
                int r = idx >> 2, kk = (idx & 3) << 2;
                float4 v = make_float4(0.f, 0.f, 0.f, 0.f);
                if (n0 + r < N)
                    v = *(const float4*)(Bm + (size_t)(n0 + r) * K + k0 + kk);
                Bs[kk + 0][r] = v.x; Bs[kk + 1][r] = v.y;
                Bs[kk + 2][r] = v.z; Bs[kk + 3][r] = v.w;
            }
        } else {
#pragma unroll
            for (int p = 0; p < 2; p++) {
                int idx = tid + p * 256;
                int kk = idx >> 5, nn = (idx & 31) << 2;
                float4 v = make_float4(0.f, 0.f, 0.f, 0.f);
                if (n0 + nn < N)
                    v = *(const float4*)(Bm + (size_t)(k0 + kk) * N + n0 + nn);
                Bs[kk][nn + 0] = v.x; Bs[kk][nn + 1] = v.y;
                Bs[kk][nn + 2] = v.z; Bs[kk][nn + 3] = v.w;
            }
        }
        __syncthreads();
#pragma unroll
        for (int kk = 0; kk < 16; kk++) {
            float a[8], b[8];
            *(float4*)&a[0] = *(const float4*)&As[kk][ty * 8];
            *(float4*)&a[4] = *(const float4*)&As[kk][ty * 8 + 4];
            *(float4*)&b[0] = *(const float4*)&Bs[kk][tx * 8];
            *(float4*)&b[4] = *(const float4*)&Bs[kk][tx * 8 + 4];
#pragma unroll
            for (int i = 0; i < 8; i++)
#pragma unroll
                for (int j = 0; j < 8; j++)
                    acc[i][j] += a[i] * b[j];
        }
        __syncthreads();
    }
#pragma unroll
    for (int i = 0; i < 8; i++) {
        int m = m0 + ty * 8 + i;
#pragma unroll
        for (int j4 = 0; j4 < 2; j4++) {
            int n = n0 + tx * 8 + j4 * 4;
            if (n < N) {
                float4 v;
                v.x = epi_f<EPI>(acc[i][j4 * 4 + 0], bias, n + 0);
                v.y = epi_f<EPI>(acc[i][j4 * 4 + 1], bias, n + 1);
                v.z = epi_f<EPI>(acc[i][j4 * 4 + 2], bias, n + 2);
                v.w = epi_f<EPI>(acc[i][j4 * 4 + 3], bias, n + 3);
                *(float4*)(Cm + (size_t)m * ldc + n) = v;
            }
        }
    }
}

// ---------------- tf32 tensor-core GEMM: C[8192,768] = A[8192,768] @ B[768,768]^T ----------------
// A,B pre-rounded to tf32-representable fp32. EPI: 0 none, 2 relu.
#define GT_K   CDIM
#define GT_N   CDIM
#define ASTR   36
#define ASZ    (128*ASTR)
#define GT_SMEM (4*ASZ*4)   // 2 stages x (A+B) = 73728 B

__device__ __forceinline__ void gt_issue(float* sm, const float* __restrict__ A,
                                         const float* __restrict__ Bm,
                                         int m0, int n0, int it, int tid)
{
    int s = it & 1;
    float* As = sm + s * ASZ;
    float* Bs = sm + 2 * ASZ + s * ASZ;
    int k0 = it * 32;
#pragma unroll
    for (int p = 0; p < 4; p++) {
        int c = tid + p * 256;
        int row = c >> 3, kc = (c & 7) << 2;
        cp16(As + row * ASTR + kc, A + (size_t)(m0 + row) * GT_K + k0 + kc);
    }
#pragma unroll
    for (int p = 0; p < 4; p++) {
        int c = tid + p * 256;
        int row = c >> 3, kc = (c & 7) << 2;
        cp16(Bs + row * ASTR + kc, Bm + (size_t)(n0 + row) * GT_K + k0 + kc);
    }
    asm volatile("cp.async.commit_group;" ::: "memory");
}

template<int EPI>
__global__ __launch_bounds__(256) void gemm_tf32_kernel(
    const float* __restrict__ A, const float* __restrict__ Bm,
    float* __restrict__ Cm)
{
    extern __shared__ __align__(16) float sm[];
    int tid = threadIdx.x;
    int lane = tid & 31, warp = tid >> 5;
    int warp_m = warp >> 2, warp_n = warp & 3;   // 2 x 4
    int m0 = blockIdx.y * 128, n0 = blockIdx.x * 128;

    // ldmatrix per-lane source rows
    int lrow = lane & 7;
    int a_m = ((lane >> 3) & 1) * 8 + lrow;
    int a_k = (lane >> 4) * 4;
    int b_k = ((lane >> 3) & 1) * 4;

    float acc[4][4][4];
#pragma unroll
    for (int i = 0; i < 4; i++)
#pragma unroll
        for (int j = 0; j < 4; j++)
#pragma unroll
            for (int q = 0; q < 4; q++) acc[i][j][q] = 0.f;

    gt_issue(sm, A, Bm, m0, n0, 0, tid);

    const int NIT = GT_K / 32;   // 24
#pragma unroll 1
    for (int it = 0; it < NIT; it++) {
        if (it + 1 < NIT) {
            gt_issue(sm, A, Bm, m0, n0, it + 1, tid);
            asm volatile("cp.async.wait_group 1;" ::: "memory");
        } else {
            asm volatile("cp.async.wait_group 0;" ::: "memory");
        }
        __syncthreads();
        int s = it & 1;
        const float* As = sm + s * ASZ;
        const float* Bs = sm + 2 * ASZ + s * ASZ;
#pragma unroll
        for (int ks = 0; ks < 4; ks++) {
            unsigned af[4][4], bf[4][2];
#pragma unroll
            for (int mi = 0; mi < 4; mi++) {
                const float* p = As + (warp_m * 64 + mi * 16 + a_m) * ASTR + ks * 8 + a_k;
                unsigned ad = (unsigned)__cvta_generic_to_shared(p);
                asm volatile("ldmatrix.sync.aligned.m8n8.x4.shared.b16 {%0,%1,%2,%3}, [%4];"
                    : "=r"(af[mi][0]), "=r"(af[mi][1]), "=r"(af[mi][2]), "=r"(af[mi][3]) : "r"(ad));
            }
#pragma unroll
            for (int ni = 0; ni < 4; ni++) {
                const float* p = Bs + (warp_n * 32 + ni * 8 + lrow) * ASTR + ks * 8 + b_k;
                unsigned ad = (unsigned)__cvta_generic_to_shared(p);
                asm volatile("ldmatrix.sync.aligned.m8n8.x2.shared.b16 {%0,%1}, [%2];"
                    : "=r"(bf[ni][0]), "=r"(bf[ni][1]) : "r"(ad));
            }
#pragma unroll
            for (int mi = 0; mi < 4; mi++)
#pragma unroll
                for (int ni = 0; ni < 4; ni++) {
                    asm volatile(
                        "mma.sync.aligned.m16n8k8.row.col.f32.tf32.tf32.f32 "
                        "{%0,%1,%2,%3}, {%4,%5,%6,%7}, {%8,%9}, {%0,%1,%2,%3};"
                        : "+f"(acc[mi][ni][0]), "+f"(acc[mi][ni][1]),
                          "+f"(acc[mi][ni][2]), "+f"(acc[mi][ni][3])
                        : "r"(af[mi][0]), "r"(af[mi][1]), "r"(af[mi][2]), "r"(af[mi][3]),
                          "r"(bf[ni][0]), "r"(bf[ni][1]));
                }
        }
        __syncthreads();
    }

    // epilogue
    int erow = lane >> 2, ecol = (lane & 3) * 2;
#pragma unroll
    for (int mi = 0; mi < 4; mi++) {
#pragma unroll
        for (int ni = 0; ni < 4; ni++) {
            int m = m0 + warp_m * 64 + mi * 16 + erow;
            int n = n0 + warp_n * 32 + ni * 8 + ecol;
            float2 v0, v1;
            v0.x = epi_f<EPI>(acc[mi][ni][0], nullptr, 0);
            v0.y = epi_f<EPI>(acc[mi][ni][1], nullptr, 0);
            v1.x = epi_f<EPI>(acc[mi][ni][2], nullptr, 0);
            v1.y = epi_f<EPI>(acc[mi][ni][3], nullptr, 0);
            *(float2*)(Cm + (size_t)m * GT_N + n) = v0;
            *(float2*)(Cm + (size_t)(m + 8) * GT_N + n) = v1;
        }
    }
}

// ---------------- K3: 5-way token-shift mixer (rounds xr/xk/xv/xg to tf32) ----------------
#define MIX5_SMEM ((160*256 + 8*160) * 4)
__global__ __launch_bounds__(256, 1) void mix5_kernel(
    const float* __restrict__ x, const float* __restrict__ xx,
    const float* __restrict__ t_arr, const float* __restrict__ w2,
    const float* __restrict__ mw, const float* __restrict__ mk,
    const float* __restrict__ mv, const float* __restrict__ mr,
    const float* __restrict__ mg,
    float* __restrict__ xw, float* __restrict__ xk, float* __restrict__ xv,
    float* __restrict__ xr, float* __restrict__ xg)
{
    extern __shared__ __align__(16) float sm[];
    float* w2s = sm;
    float* ts2 = sm + 160 * 256;
    int tid = threadIdx.x;
    int c = blockIdx.x * 256 + tid;
    int rbase = blockIdx.y * 64;

    for (int j = 0; j < 160; j++) w2s[j * 256 + tid] = w2[j * CDIM + c];
    float cw = mw[c], ck = mk[c], cv = mv[c], cr = mr[c], cg = mg[c];
    __syncthreads();

#pragma unroll 1
    for (int grp = 0; grp < 8; grp++) {
        int row0 = rbase + grp * 8;
        for (int i = tid; i < 8 * 160; i += 256)
            ts2[i] = t_arr[(size_t)(row0 + i / 160) * 160 + (i % 160)];
        __syncthreads();

        float acc[8][5];
#pragma unroll
        for (int r = 0; r < 8; r++)
#pragma unroll
            for (int f = 0; f < 5; f++) acc[r][f] = 0.f;

#pragma unroll
        for (int f = 0; f < 5; f++) {
#pragma unroll 2
            for (int j4 = 0; j4 < 8; j4++) {
                int jb = f * 32 + j4 * 4;
                float w0 = w2s[(jb + 0) * 256 + tid];
                float w1 = w2s[(jb + 1) * 256 + tid];
                float w2v = w2s[(jb + 2) * 256 + tid];
                float w3 = w2s[(jb + 3) * 256 + tid];
#pragma unroll
                for (int r = 0; r < 8; r++) {
                    float4 tv = *(const float4*)&ts2[r * 160 + jb];
                    acc[r][f] += tv.x * w0 + tv.y * w1 + tv.z * w2v + tv.w * w3;
                }
            }
        }
#pragma unroll
        for (int r = 0; r < 8; r++) {
            size_t gi = (size_t)(row0 + r) * CDIM + c;
            float xval = x[gi], xxval = xx[gi];
            xw[gi] = xval + xxval * (cw + acc[r][0]);
            xk[gi] = tf32r(xval + xxval * (ck + acc[r][1]));
            xv[gi] = tf32r(xval + xxval * (cv + acc[r][2]));
            xr[gi] = tf32r(xval + xxval * (cr + acc[r][3]));
            xg[gi] = tf32r(xval + xxval * (cg + acc[r][4]));
        }
        __syncthreads();
    }
}

// ---------------- K4: WKV6 recurrence ----------------
__device__ __forceinline__ void wkv_issue(int ci, float* rsb, float* ksb,
        float* vsb, float* wsb,
        const float* rp, const float* kp, const float* vp, const float* wpp,
        size_t base, int tid)
{
#pragma unroll
    for (int p = 0; p < 2; p++) {
        int idx = tid + p * 256;
        int arr = idx >> 7;
        int rem = idx & 127;
        int tc = rem >> 4, c4 = (rem & 15) << 2;
        size_t gofs = base + (size_t)(ci * 8 + tc) * CDIM + c4;
        float* dst; const float* src;
        if (arr == 0)      { dst = rsb + tc * 64 + c4; src = rp  + gofs; }
        else if (arr == 1) { dst = ksb + tc * 64 + c4; src = kp  + gofs; }
        else if (arr == 2) { dst = vsb + tc * 64 + c4; src = vp  + gofs; }
        else               { dst = wsb + tc * 64 + c4; src = wpp + gofs; }
        cp16(dst, src);
    }
    asm volatile("cp.async.commit_group;" ::: "memory");
}

__global__ __launch_bounds__(256, 1) void wkv6_kernel(
    const float* __restrict__ rp, const float* __restrict__ kp,
    const float* __restrict__ vp, const float* __restrict__ wp_,
    const float* __restrict__ up, float* __restrict__ yp)
{
    __shared__ __align__(16) float rs[2][512], ks[2][512], vs[2][512], ws[2][512];
    __shared__ float us[64], ruks[8];
    int tid = threadIdx.x;
    int b = blockIdx.x / NHEAD, h = blockIdx.x % NHEAD;
    size_t base = (size_t)b * TDIM * CDIM + h * HS;
    if (tid < 64) us[tid] = up[h * HS + tid];
    int i = tid >> 2, jq = tid & 3;
    int lane = tid & 31, warp = tid >> 5;

    float S[16];
#pragma unroll
    for (int q = 0; q < 16; q++) S[q] = 0.f;

    wkv_issue(0, rs[0], ks[0], vs[0], ws[0], rp, kp, vp, wp_, base, tid);

#pragma unroll 1
    for (int ci = 0; ci < TDIM / 8; ci++) {
        int buf = ci & 1;
        asm volatile("cp.async.wait_group 0;" ::: "memory");
        __syncthreads();
        for (int idx = tid; idx < 512; idx += 256)
            ws[buf][idx] = expf(-expf(ws[buf][idx]));
        {
            float p = rs[buf][warp * 64 + lane] * us[lane] * ks[buf][warp * 64 + lane]
                    + rs[buf][warp * 64 + 32 + lane] * us[32 + lane] * ks[buf][warp * 64 + 32 + lane];
#pragma unroll
            for (int o = 16; o; o >>= 1) p += __shfl_xor_sync(0xffffffffu, p, o);
            if (lane == 0) ruks[warp] = p;
        }
        __syncthreads();
        if (ci + 1 < TDIM / 8) {
            int nb = buf ^ 1;
            wkv_issue(ci + 1, rs[nb], ks[nb], vs[nb], ws[nb], rp, kp, vp, wp_, base, tid);
        }
#pragma unroll 1
        for (int tc = 0; tc < 8; tc++) {
            float vi = vs[buf][tc * 64 + i];
            const float4* r4 = (const float4*)&rs[buf][tc * 64 + jq * 16];
            const float4* k4 = (const float4*)&ks[buf][tc * 64 + jq * 16];
            const float4* w4 = (const float4*)&ws[buf][tc * 64 + jq * 16];
            float yps = 0.f;
#pragma unroll
            for (int q = 0; q < 4; q++) {
                float4 rv = r4[q], kv = k4[q], wv = w4[q];
                yps += rv.x * S[q * 4 + 0]; S[q * 4 + 0] = wv.x * S[q * 4 + 0] + kv.x * vi;
                yps += rv.y * S[q * 4 + 1]; S[q * 4 + 1] = wv.y * S[q * 4 + 1] + kv.y * vi;
                yps += rv.z * S[q * 4 + 2]; S[q * 4 + 2] = wv.z * S[q * 4 + 2] + kv.z * vi;
                yps += rv.w * S[q * 4 + 3]; S[q * 4 + 3] = wv.w * S[q * 4 + 3] + kv.w * vi;
            }
            yps += __shfl_xor_sync(0xffffffffu, yps, 1);
            yps += __shfl_xor_sync(0xffffffffu, yps, 2);
            if (jq == 0)
                yp[base + (size_t)(ci * 8 + tc) * CDIM + i] = yps + vi * ruks[tc];
        }
    }
}

// ---------------- K5: per-head GroupNorm * g (rounds to tf32) ----------------
__global__ void gn_mul_kernel(const float* __restrict__ y,
                              const float* __restrict__ lw, const float* __restrict__ lb,
                              const float* __restrict__ g, float* __restrict__ out)
{
    int row = blockIdx.x;
    int warp = threadIdx.x >> 5, lane = threadIdx.x & 31;
    size_t o = (size_t)row * CDIM + warp * HS;
    float v0 = y[o + lane], v1 = y[o + 32 + lane];
    float s = v0 + v1, ss = v0 * v0 + v1 * v1;
#pragma unroll
    for (int off = 16; off; off >>= 1) {
        s  += __shfl_xor_sync(0xffffffffu, s,  off);
        ss += __shfl_xor_sync(0xffffffffu, ss, off);
    }
    float mean = s * (1.f / HS);
    float var  = ss * (1.f / HS) - mean * mean;
    float inv  = rsqrtf(var + 1e-5f);
    int c0 = warp * HS + lane, c1 = c0 + 32;
    float n0 = (v0 - mean) * inv * lw[c0] + lb[c0];
    float n1 = (v1 - mean) * inv * lw[c1] + lb[c1];
    out[o + lane]      = tf32r(n0 * g[o + lane]);
    out[o + 32 + lane] = tf32r(n1 * g[o + 32 + lane]);
}

// ---------------- launcher ----------------
extern "C" void kernel_launch(void* const* d_in, const int* in_sizes, int n_in,
                              void* d_out, int out_size)
{
    const float* x          = (const float*)d_in[0];
    const float* W_r        = (const float*)d_in[1];
    const float* W_k        = (const float*)d_in[2];
    const float* W_v        = (const float*)d_in[3];
    const float* W_g        = (const float*)d_in[4];
    const float* W_o        = (const float*)d_in[5];
    const float* maa_x      = (const float*)d_in[6];
    const float* maa_w      = (const float*)d_in[7];
    const float* maa_k      = (const float*)d_in[8];
    const float* maa_v      = (const float*)d_in[9];
    const float* maa_r      = (const float*)d_in[10];
    const float* maa_g      = (const float*)d_in[11];
    const float* maa_w1     = (const float*)d_in[12];
    const float* maa_w2     = (const float*)d_in[13];
    const float* time_decay = (const float*)d_in[14];
    const float* dec_w1     = (const float*)d_in[15];
    const float* dec_w2     = (const float*)d_in[16];
    const float* faaaa      = (const float*)d_in[17];
    const float* ln_w       = (const float*)d_in[18];
    const float* ln_b       = (const float*)d_in[19];
    float* out = (float*)d_out;

    float *xx, *xxx, *tb, *xw, *xk, *xv, *xr, *xg, *rb, *kb, *vb, *gb, *h1, *wb, *yb, *yg, *Wc;
    cudaGetSymbolAddress((void**)&xx,  g_xx);
    cudaGetSymbolAddress((void**)&xxx, g_xxx);
    cudaGetSymbolAddress((void**)&tb,  g_t);
    cudaGetSymbolAddress((void**)&xw,  g_xw);
    cudaGetSymbolAddress((void**)&xk,  g_xk);
    cudaGetSymbolAddress((void**)&xv,  g_xv);
    cudaGetSymbolAddress((void**)&xr,  g_xr);
    cudaGetSymbolAddress((void**)&xg,  g_xg);
    cudaGetSymbolAddress((void**)&rb,  g_r);
    cudaGetSymbolAddress((void**)&kb,  g_k);
    cudaGetSymbolAddress((void**)&vb,  g_v);
    cudaGetSymbolAddress((void**)&gb,  g_g);
    cudaGetSymbolAddress((void**)&h1,  g_h1);
    cudaGetSymbolAddress((void**)&wb,  g_w);
    cudaGetSymbolAddress((void**)&yb,  g_y);
    cudaGetSymbolAddress((void**)&yg,  g_yg);
    cudaGetSymbolAddress((void**)&Wc,  g_Wc);

    const int NW = CDIM * CDIM;
    float* Wr_c = Wc + 0 * NW;
    float* Wk_c = Wc + 1 * NW;
    float* Wv_c = Wc + 2 * NW;
    float* Wg_c = Wc + 3 * NW;
    float* Wo_c = Wc + 4 * NW;

    cudaFuncSetAttribute(mix5_kernel, cudaFuncAttributeMaxDynamicSharedMemorySize, MIX5_SMEM);
    cudaFuncSetAttribute(gemm_tf32_kernel<0>, cudaFuncAttributeMaxDynamicSharedMemorySize, GT_SMEM);
    cudaFuncSetAttribute(gemm_tf32_kernel<2>, cudaFuncAttributeMaxDynamicSharedMemorySize, GT_SMEM);

    round_w_kernel<<<(5 * NW + 255) / 256, 256>>>(W_r, W_k, W_v, W_g, W_o, Wc);

    int total = NR * CDIM;
    shift_mix_kernel<<<(total + 255) / 256, 256>>>(x, maa_x, xx, xxx, total);

    // t = tanh(xxx @ maa_w1)   [NR,160]
    {
        dim3 grid(2, NR / 128);
        gemm_kernel<1, false><<<grid, 256>>>(xxx, CDIM, maa_w1, tb, 160, 160, CDIM, nullptr);
    }

    // xw..xg via 5-way mixer
    {
        dim3 grid(3, NR / 64);
        mix5_kernel<<<grid, 256, MIX5_SMEM>>>(x, xx, tb, maa_w2,
            maa_w, maa_k, maa_v, maa_r, maa_g, xw, xk, xv, xr, xg);
    }

    dim3 gtc(6, NR / 128);
    gemm_tf32_kernel<0><<<gtc, 256, GT_SMEM>>>(xr, Wr_c, rb);
    gemm_tf32_kernel<0><<<gtc, 256, GT_SMEM>>>(xk, Wk_c, kb);
    gemm_tf32_kernel<0><<<gtc, 256, GT_SMEM>>>(xv, Wv_c, vb);
    gemm_tf32_kernel<2><<<gtc, 256, GT_SMEM>>>(xg, Wg_c, gb);

    // h1 = tanh(xw @ dec_w1)  [NR,64]
    {
        dim3 grid(1, NR / 128);
        gemm_kernel<1, false><<<grid, 256>>>(xw, CDIM, dec_w1, h1, 64, 64, CDIM, nullptr);
    }
    // w = time_decay + h1 @ dec_w2  [NR,768]
    {
        dim3 gcc(6, NR / 128);
        gemm_kernel<3, false><<<gcc, 256>>>(h1, 64, dec_w2, wb, CDIM, CDIM, 64, time_decay);
    }

    // WKV6
    wkv6_kernel<<<8 * NHEAD, 256>>>(rb, kb, vb, wb, faaaa, yb);

    // GroupNorm * g
    gn_mul_kernel<<<NR, 384>>>(yb, ln_w, ln_b, gb, yg);

    // out = yg @ W_o.T
    gemm_tf32_kernel<0><<<gtc, 256, GT_SMEM>>>(yg, Wo_c, out);
}

// round 6
// speedup vs baseline: 1.1711x; 1.1711x over previous
#include <cuda_runtime.h>
#include <math.h>

#define TDIM 1024
#define CDIM 768
#define PH 32
#define PW 32
#define NHEAD 12
#define HS 64
#define NR (8*1024)

__device__ float g_xx [NR*CDIM];
__device__ float g_xxx[NR*CDIM];
__device__ float g_t  [NR*160];
__device__ float g_xw [NR*CDIM];
__device__ float g_xk [NR*CDIM];
__device__ float g_xv [NR*CDIM];
__device__ float g_xr [NR*CDIM];
__device__ float g_xg [NR*CDIM];
__device__ float g_r  [NR*CDIM];
__device__ float g_k  [NR*CDIM];
__device__ float g_v  [NR*CDIM];
__device__ float g_g  [NR*CDIM];
__device__ float g_h1 [NR*64];
__device__ float g_w  [NR*CDIM];
__device__ float g_y  [NR*CDIM];
__device__ float g_yg [NR*CDIM];
__device__ float g_Wc [5*CDIM*CDIM];          // tf32-rounded big weights
__device__ float g_Wt [160*CDIM + 64*CDIM + CDIM*64];  // transposed+rounded small weights

__device__ __forceinline__ float tf32r(float x) {
    unsigned u;
    asm("cvt.rna.tf32.f32 %0, %1;" : "=r"(u) : "f"(x));
    return __uint_as_float(u);
}

__device__ __forceinline__ void cp16(void* dst, const void* src) {
    unsigned d = (unsigned)__cvta_generic_to_shared(dst);
    asm volatile("cp.async.cg.shared.global [%0], [%1], 16;" :: "r"(d), "l"(src) : "memory");
}
__device__ __forceinline__ void cp16z(void* dst, const void* src, int sz) {
    unsigned d = (unsigned)__cvta_generic_to_shared(dst);
    asm volatile("cp.async.cg.shared.global [%0], [%1], 16, %2;" :: "r"(d), "l"(src), "r"(sz) : "memory");
}

// ---------------- K0a: round big weights ----------------
__global__ void round_w_kernel(const float* __restrict__ w0, const float* __restrict__ w1,
                               const float* __restrict__ w2, const float* __restrict__ w3,
                               const float* __restrict__ w4, float* __restrict__ out)
{
    int idx = blockIdx.x * blockDim.x + threadIdx.x;
    const int NW = CDIM * CDIM;
    if (idx >= 5 * NW) return;
    int m = idx / NW, r = idx % NW;
    const float* src = (m == 0) ? w0 : (m == 1) ? w1 : (m == 2) ? w2 : (m == 3) ? w3 : w4;
    out[idx] = tf32r(src[r]);
}

// ---------------- K0b: transpose + round small weights ----------------
// in [R, Ccols] -> out [Ccols, R]
__global__ void transpose_round_kernel(const float* __restrict__ in, float* __restrict__ out,
                                       int R, int Ccols)
{
    int idx = blockIdx.x * blockDim.x + threadIdx.x;
    if (idx >= R * Ccols) return;
    int r = idx / Ccols, c = idx % Ccols;
    out[c * R + r] = tf32r(in[idx]);
}

// ---------------- K1: q_shift + maa_x mix ----------------
__global__ void shift_mix_kernel(const float* __restrict__ x,
                                 const float* __restrict__ maa_x,
                                 float* __restrict__ xx, float* __restrict__ xxx,
                                 int total)
{
    int idx = blockIdx.x * blockDim.x + threadIdx.x;
    if (idx >= total) return;
    int c = idx % CDIM;
    int t = (idx / CDIM) % TDIM;
    int b = idx / (CDIM * TDIM);
    int d  = c & (HS - 1);
    int hh = t >> 5, ww = t & 31;
    float sh = 0.f;
    int st = -1;
    if (d < 16)      { if (ww >= 1)      st = t - 1;  }
    else if (d < 32) { if (ww < PW - 1)  st = t + 1;  }
    else if (d < 48) { if (hh >= 1)      st = t - PW; }
    else             { if (hh < PH - 1)  st = t + PW; }
    if (st >= 0) sh = x[((size_t)b * TDIM + st) * CDIM + c];
    float xv = x[idx];
    float dd = sh - xv;
    xx[idx]  = dd;
    xxx[idx] = tf32r(xv + dd * maa_x[c]);   // feeds tf32 GEMM only
}

// ---------------- tf32 tensor-core GEMM (generalized) ----------------
// C[NR, N] = epi( A[NR, K] @ B[N, K]^T ), A lda == K, B tf32-rounded.
// EPI: 0 none, 1 tanh, 2 relu, 3 +bias[n], 4 tanh then tf32 round
#define ASTR   36
#define ASZ    (128*ASTR)
#define GT_SMEM (4*ASZ*4)   // 73728 B

template<int EPI>
__device__ __forceinline__ float epi_f(float a, const float* bias, int n) {
    if (EPI == 1) return tanhf(a);
    if (EPI == 2) return fmaxf(a, 0.f);
    if (EPI == 3) return a + bias[n];
    if (EPI == 4) return tf32r(tanhf(a));
    return a;
}

__device__ __forceinline__ void gt_issue(float* sm, const float* __restrict__ A,
                                         const float* __restrict__ Bm,
                                         int m0, int n0, int it, int tid, int N, int K)
{
    int s = it & 1;
    float* As = sm + s * ASZ;
    float* Bs = sm + 2 * ASZ + s * ASZ;
    int k0 = it * 32;
#pragma unroll
    for (int p = 0; p < 4; p++) {
        int c = tid + p * 256;
        int row = c >> 3, kc = (c & 7) << 2;
        cp16(As + row * ASTR + kc, A + (size_t)(m0 + row) * K + k0 + kc);
    }
#pragma unroll
    for (int p = 0; p < 4; p++) {
        int c = tid + p * 256;
        int row = c >> 3, kc = (c & 7) << 2;
        int valid = (n0 + row) < N;
        const float* src = Bm + (valid ? ((size_t)(n0 + row) * K + k0 + kc) : 0);
        cp16z(Bs + row * ASTR + kc, src, valid ? 16 : 0);
    }
    asm volatile("cp.async.commit_group;" ::: "memory");
}

template<int EPI>
__global__ __launch_bounds__(256) void gemm_tf32_kernel(
    const float* __restrict__ A, const float* __restrict__ Bm,
    float* __restrict__ Cm, int N, int K, const float* __restrict__ bias)
{
    extern __shared__ __align__(16) float sm[];
    int tid = threadIdx.x;
    int lane = tid & 31, warp = tid >> 5;
    int warp_m = warp >> 2, warp_n = warp & 3;   // 2 x 4
    int m0 = blockIdx.y * 128, n0 = blockIdx.x * 128;

    int lrow = lane & 7;
    int a_m = ((lane >> 3) & 1) * 8 + lrow;
    int a_k = (lane >> 4) * 4;
    int b_k = ((lane >> 3) & 1) * 4;

    float acc[4][4][4];
#pragma unroll
    for (int i = 0; i < 4; i++)
#pragma unroll
        for (int j = 0; j < 4; j++)
#pragma unroll
            for (int q = 0; q < 4; q++) acc[i][j][q] = 0.f;

    gt_issue(sm, A, Bm, m0, n0, 0, tid, N, K);

    const int NIT = K / 32;
#pragma unroll 1
    for (int it = 0; it < NIT; it++) {
        if (it + 1 < NIT) {
            gt_issue(sm, A, Bm, m0, n0, it + 1, tid, N, K);
            asm volatile("cp.async.wait_group 1;" ::: "memory");
        } else {
            asm volatile("cp.async.wait_group 0;" ::: "memory");
        }
        __syncthreads();
        int s = it & 1;
        const float* As = sm + s * ASZ;
        const float* Bs = sm + 2 * ASZ + s * ASZ;
#pragma unroll
        for (int ks = 0; ks < 4; ks++) {
            unsigned af[4][4], bf[4][2];
#pragma unroll
            for (int mi = 0; mi < 4; mi++) {
                const float* p = As + (warp_m * 64 + mi * 16 + a_m) * ASTR + ks * 8 + a_k;
                unsigned ad = (unsigned)__cvta_generic_to_shared(p);
                asm volatile("ldmatrix.sync.aligned.m8n8.x4.shared.b16 {%0,%1,%2,%3}, [%4];"
                    : "=r"(af[mi][0]), "=r"(af[mi][1]), "=r"(af[mi][2]), "=r"(af[mi][3]) : "r"(ad));
            }
#pragma unroll
            for (int ni = 0; ni < 4; ni++) {
                const float* p = Bs + (warp_n * 32 + ni * 8 + lrow) * ASTR + ks * 8 + b_k;
                unsigned ad = (unsigned)__cvta_generic_to_shared(p);
                asm volatile("ldmatrix.sync.aligned.m8n8.x2.shared.b16 {%0,%1}, [%2];"
                    : "=r"(bf[ni][0]), "=r"(bf[ni][1]) : "r"(ad));
            }
#pragma unroll
            for (int mi = 0; mi < 4; mi++)
#pragma unroll
                for (int ni = 0; ni < 4; ni++) {
                    asm volatile(
                        "mma.sync.aligned.m16n8k8.row.col.f32.tf32.tf32.f32 "
                        "{%0,%1,%2,%3}, {%4,%5,%6,%7}, {%8,%9}, {%0,%1,%2,%3};"
                        : "+f"(acc[mi][ni][0]), "+f"(acc[mi][ni][1]),
                          "+f"(acc[mi][ni][2]), "+f"(acc[mi][ni][3])
                        : "r"(af[mi][0]), "r"(af[mi][1]), "r"(af[mi][2]), "r"(af[mi][3]),
                          "r"(bf[ni][0]), "r"(bf[ni][1]));
                }
        }
        __syncthreads();
    }

    int erow = lane >> 2, ecol = (lane & 3) * 2;
#pragma unroll
    for (int mi = 0; mi < 4; mi++) {
#pragma unroll
        for (int ni = 0; ni < 4; ni++) {
            int m = m0 + warp_m * 64 + mi * 16 + erow;
            int n = n0 + warp_n * 32 + ni * 8 + ecol;
            if (n < N) {
                float2 v0, v1;
                v0.x = epi_f<EPI>(acc[mi][ni][0], bias, n);
                v0.y = epi_f<EPI>(acc[mi][ni][1], bias, n + 1);
                v1.x = epi_f<EPI>(acc[mi][ni][2], bias, n);
                v1.y = epi_f<EPI>(acc[mi][ni][3], bias, n + 1);
                *(float2*)(Cm + (size_t)m * N + n) = v0;
                *(float2*)(Cm + (size_t)(m + 8) * N + n) = v1;
            }
        }
    }
}

// ---------------- K3: 5-way token-shift mixer (64ch x 64row blocks) ----------------
#define MIX5_SMEM ((160*64 + 8*160) * 4)   // 46080 B
__global__ __launch_bounds__(256) void mix5_kernel(
    const float* __restrict__ x, const float* __restrict__ xx,
    const float* __restrict__ t_arr, const float* __restrict__ w2,
    const float* __restrict__ mw, const float* __restrict__ mk,
    const float* __restrict__ mv, const float* __restrict__ mr,
    const float* __restrict__ mg,
    float* __restrict__ xw, float* __restrict__ xk, float* __restrict__ xv,
    float* __restrict__ xr, float* __restrict__ xg)
{
    extern __shared__ __align__(16) float sm[];
    float* w2s = sm;                 // [160][64]
    float* ts2 = sm + 160 * 64;      // [8][160]
    int tid = threadIdx.x;
    int c0 = blockIdx.x * 64;
    int rbase = blockIdx.y * 64;
    int c = tid & 63, rr = tid >> 6;

    for (int i = tid; i < 160 * 64; i += 256)
        w2s[i] = w2[(i >> 6) * CDIM + c0 + (i & 63)];
    float cw = mw[c0 + c], ck = mk[c0 + c], cv = mv[c0 + c],
          cr = mr[c0 + c], cg = mg[c0 + c];
    __syncthreads();

#pragma unroll 1
    for (int grp = 0; grp < 8; grp++) {
        int row0 = rbase + grp * 8;
        for (int i = tid; i < 8 * 160; i += 256)
            ts2[i] = t_arr[(size_t)(row0 + i / 160) * 160 + (i % 160)];
        __syncthreads();

        float acc[2][5];
#pragma unroll
        for (int r = 0; r < 2; r++)
#pragma unroll
            for (int f = 0; f < 5; f++) acc[r][f] = 0.f;

#pragma unroll
        for (int f = 0; f < 5; f++) {
#pragma unroll
            for (int j4 = 0; j4 < 8; j4++) {
                int jb = f * 32 + j4 * 4;
                float w0 = w2s[(jb + 0) * 64 + c];
                float w1 = w2s[(jb + 1) * 64 + c];
                float w2v = w2s[(jb + 2) * 64 + c];
                float w3 = w2s[(jb + 3) * 64 + c];
#pragma unroll
                for (int r = 0; r < 2; r++) {
                    float4 tv = *(const float4*)&ts2[(rr * 2 + r) * 160 + jb];
                    acc[r][f] += tv.x * w0 + tv.y * w1 + tv.z * w2v + tv.w * w3;
                }
            }
        }
#pragma unroll
        for (int r = 0; r < 2; r++) {
            size_t gi = (size_t)(row0 + rr * 2 + r) * CDIM + c0 + c;
            float xval = x[gi], xxval = xx[gi];
            xw[gi] = tf32r(xval + xxval * (cw + acc[r][0]));
            xk[gi] = tf32r(xval + xxval * (ck + acc[r][1]));
            xv[gi] = tf32r(xval + xxval * (cv + acc[r][2]));
            xr[gi] = tf32r(xval + xxval * (cr + acc[r][3]));
            xg[gi] = tf32r(xval + xxval * (cg + acc[r][4]));
        }
        __syncthreads();
    }
}

// ---------------- K4: WKV6 recurrence ----------------
__device__ __forceinline__ void wkv_issue(int ci, float* rsb, float* ksb,
        float* vsb, float* wsb,
        const float* rp, const float* kp, const float* vp, const float* wpp,
        size_t base, int tid)
{
#pragma unroll
    for (int p = 0; p < 2; p++) {
        int idx = tid + p * 256;
        int arr = idx >> 7;
        int rem = idx & 127;
        int tc = rem >> 4, c4 = (rem & 15) << 2;
        size_t gofs = base + (size_t)(ci * 8 + tc) * CDIM + c4;
        float* dst; const float* src;
        if (arr == 0)      { dst = rsb + tc * 64 + c4; src = rp  + gofs; }
        else if (arr == 1) { dst = ksb + tc * 64 + c4; src = kp  + gofs; }
        else if (arr == 2) { dst = vsb + tc * 64 + c4; src = vp  + gofs; }
        else               { dst = wsb + tc * 64 + c4; src = wpp + gofs; }
        cp16(dst, src);
    }
    asm volatile("cp.async.commit_group;" ::: "memory");
}

__global__ __launch_bounds__(256, 1) void wkv6_kernel(
    const float* __restrict__ rp, const float* __restrict__ kp,
    const float* __restrict__ vp, const float* __restrict__ wp_,
    const float* __restrict__ up, float* __restrict__ yp)
{
    __shared__ __align__(16) float rs[2][512], ks[2][512], vs[2][512], ws[2][512];
    __shared__ float us[64], ruks[8];
    int tid = threadIdx.x;
    int b = blockIdx.x / NHEAD, h = blockIdx.x % NHEAD;
    size_t base = (size_t)b * TDIM * CDIM + h * HS;
    if (tid < 64) us[tid] = up[h * HS + tid];
    int i = tid >> 2, jq = tid & 3;
    int lane = tid & 31, warp = tid >> 5;

    float S[16];
#pragma unroll
    for (int q = 0; q < 16; q++) S[q] = 0.f;

    wkv_issue(0, rs[0], ks[0], vs[0], ws[0], rp, kp, vp, wp_, base, tid);

#pragma unroll 1
    for (int ci = 0; ci < TDIM / 8; ci++) {
        int buf = ci & 1;
        asm volatile("cp.async.wait_group 0;" ::: "memory");
        __syncthreads();
        for (int idx = tid; idx < 512; idx += 256)
            ws[buf][idx] = expf(-expf(ws[buf][idx]));
        {
            float p = rs[buf][warp * 64 + lane] * us[lane] * ks[buf][warp * 64 + lane]
                    + rs[buf][warp * 64 + 32 + lane] * us[32 + lane] * ks[buf][warp * 64 + 32 + lane];
#pragma unroll
            for (int o = 16; o; o >>= 1) p += __shfl_xor_sync(0xffffffffu, p, o);
            if (lane == 0) ruks[warp] = p;
        }
        __syncthreads();
        if (ci + 1 < TDIM / 8) {
            int nb = buf ^ 1;
            wkv_issue(ci + 1, rs[nb], ks[nb], vs[nb], ws[nb], rp, kp, vp, wp_, base, tid);
        }
#pragma unroll 1
        for (int tc = 0; tc < 8; tc++) {
            float vi = vs[buf][tc * 64 + i];
            const float4* r4 = (const float4*)&rs[buf][tc * 64 + jq * 16];
            const float4* k4 = (const float4*)&ks[buf][tc * 64 + jq * 16];
            const float4* w4 = (const float4*)&ws[buf][tc * 64 + jq * 16];
            float yps = 0.f;
#pragma unroll
            for (int q = 0; q < 4; q++) {
                float4 rv = r4[q], kv = k4[q], wv = w4[q];
                yps += rv.x * S[q * 4 + 0]; S[q * 4 + 0] = wv.x * S[q * 4 + 0] + kv.x * vi;
                yps += rv.y * S[q * 4 + 1]; S[q * 4 + 1] = wv.y * S[q * 4 + 1] + kv.y * vi;
                yps += rv.z * S[q * 4 + 2]; S[q * 4 + 2] = wv.z * S[q * 4 + 2] + kv.z * vi;
                yps += rv.w * S[q * 4 + 3]; S[q * 4 + 3] = wv.w * S[q * 4 + 3] + kv.w * vi;
            }
            yps += __shfl_xor_sync(0xffffffffu, yps, 1);
            yps += __shfl_xor_sync(0xffffffffu, yps, 2);
            if (jq == 0)
                yp[base + (size_t)(ci * 8 + tc) * CDIM + i] = yps + vi * ruks[tc];
        }
    }
}

// ---------------- K5: per-head GroupNorm * g (rounds to tf32) ----------------
__global__ void gn_mul_kernel(const float* __restrict__ y,
                              const float* __restrict__ lw, const float* __restrict__ lb,
                              const float* __restrict__ g, float* __restrict__ out)
{
    int row = blockIdx.x;
    int warp = threadIdx.x >> 5, lane = threadIdx.x & 31;
    size_t o = (size_t)row * CDIM + warp * HS;
    float v0 = y[o + lane], v1 = y[o + 32 + lane];
    float s = v0 + v1, ss = v0 * v0 + v1 * v1;
#pragma unroll
    for (int off = 16; off; off >>= 1) {
        s  += __shfl_xor_sync(0xffffffffu, s,  off);
        ss += __shfl_xor_sync(0xffffffffu, ss, off);
    }
    float mean = s * (1.f / HS);
    float var  = ss * (1.f / HS) - mean * mean;
    float inv  = rsqrtf(var + 1e-5f);
    int c0 = warp * HS + lane, c1 = c0 + 32;
    float n0 = (v0 - mean) * inv * lw[c0] + lb[c0];
    float n1 = (v1 - mean) * inv * lw[c1] + lb[c1];
    out[o + lane]      = tf32r(n0 * g[o + lane]);
    out[o + 32 + lane] = tf32r(n1 * g[o + 32 + lane]);
}

// ---------------- launcher ----------------
extern "C" void kernel_launch(void* const* d_in, const int* in_sizes, int n_in,
                              void* d_out, int out_size)
{
    const float* x          = (const float*)d_in[0];
    const float* W_r        = (const float*)d_in[1];
    const float* W_k        = (const float*)d_in[2];
    const float* W_v        = (const float*)d_in[3];
    const float* W_g        = (const float*)d_in[4];
    const float* W_o        = (const float*)d_in[5];
    const float* maa_x      = (const float*)d_in[6];
    const float* maa_w      = (const float*)d_in[7];
    const float* maa_k      = (const float*)d_in[8];
    const float* maa_v      = (const float*)d_in[9];
    const float* maa_r      = (const float*)d_in[10];
    const float* maa_g      = (const float*)d_in[11];
    const float* maa_w1     = (const float*)d_in[12];
    const float* maa_w2     = (const float*)d_in[13];
    const float* time_decay = (const float*)d_in[14];
    const float* dec_w1     = (const float*)d_in[15];
    const float* dec_w2     = (const float*)d_in[16];
    const float* faaaa      = (const float*)d_in[17];
    const float* ln_w       = (const float*)d_in[18];
    const float* ln_b       = (const float*)d_in[19];
    float* out = (float*)d_out;

    float *xx, *xxx, *tb, *xw, *xk, *xv, *xr, *xg, *rb, *kb, *vb, *gb, *h1, *wb, *yb, *yg, *Wc, *Wt;
    cudaGetSymbolAddress((void**)&xx,  g_xx);
    cudaGetSymbolAddress((void**)&xxx, g_xxx);
    cudaGetSymbolAddress((void**)&tb,  g_t);
    cudaGetSymbolAddress((void**)&xw,  g_xw);
    cudaGetSymbolAddress((void**)&xk,  g_xk);
    cudaGetSymbolAddress((void**)&xv,  g_xv);
    cudaGetSymbolAddress((void**)&xr,  g_xr);
    cudaGetSymbolAddress((void**)&xg,  g_xg);
    cudaGetSymbolAddress((void**)&rb,  g_r);
    cudaGetSymbolAddress((void**)&kb,  g_k);
    cudaGetSymbolAddress((void**)&vb,  g_v);
    cudaGetSymbolAddress((void**)&gb,  g_g);
    cudaGetSymbolAddress((void**)&h1,  g_h1);
    cudaGetSymbolAddress((void**)&wb,  g_w);
    cudaGetSymbolAddress((void**)&yb,  g_y);
    cudaGetSymbolAddress((void**)&yg,  g_yg);
    cudaGetSymbolAddress((void**)&Wc,  g_Wc);
    cudaGetSymbolAddress((void**)&Wt,  g_Wt);

    const int NW = CDIM * CDIM;
    float* Wr_c = Wc + 0 * NW;
    float* Wk_c = Wc + 1 * NW;
    float* Wv_c = Wc + 2 * NW;
    float* Wg_c = Wc + 3 * NW;
    float* Wo_c = Wc + 4 * NW;
    float* W1t  = Wt;                         // [160, 768]
    float* D1t  = Wt + 160 * CDIM;            // [64, 768]
    float* D2t  = Wt + 160 * CDIM + 64 * CDIM;// [768, 64]

    cudaFuncSetAttribute(mix5_kernel, cudaFuncAttributeMaxDynamicSharedMemorySize, MIX5_SMEM);
    cudaFuncSetAttribute(gemm_tf32_kernel<0>, cudaFuncAttributeMaxDynamicSharedMemorySize, GT_SMEM);
    cudaFuncSetAttribute(gemm_tf32_kernel<1>, cudaFuncAttributeMaxDynamicSharedMemorySize, GT_SMEM);
    cudaFuncSetAttribute(gemm_tf32_kernel<2>, cudaFuncAttributeMaxDynamicSharedMemorySize, GT_SMEM);
    cudaFuncSetAttribute(gemm_tf32_kernel<3>, cudaFuncAttributeMaxDynamicSharedMemorySize, GT_SMEM);
    cudaFuncSetAttribute(gemm_tf32_kernel<4>, cudaFuncAttributeMaxDynamicSharedMemorySize, GT_SMEM);

    round_w_kernel<<<(5 * NW + 255) / 256, 256>>>(W_r, W_k, W_v, W_g, W_o, Wc);
    transpose_round_kernel<<<(CDIM * 160 + 255) / 256, 256>>>(maa_w1, W1t, CDIM, 160);
    transpose_round_kernel<<<(CDIM * 64 + 255) / 256, 256>>>(dec_w1, D1t, CDIM, 64);
    transpose_round_kernel<<<(64 * CDIM + 255) / 256, 256>>>(dec_w2, D2t, 64, CDIM);

    int total = NR * CDIM;
    shift_mix_kernel<<<(total + 255) / 256, 256>>>(x, maa_x, xx, xxx, total);

    // t = tanh(xxx @ maa_w1)   [NR,160]
    {
        dim3 grid(2, NR / 128);
        gemm_tf32_kernel<1><<<grid, 256, GT_SMEM>>>(xxx, W1t, tb, 160, CDIM, nullptr);
    }

    // xw..xg via 5-way mixer
    {
        dim3 grid(CDIM / 64, NR / 64);
        mix5_kernel<<<grid, 256, MIX5_SMEM>>>(x, xx, tb, maa_w2,
            maa_w, maa_k, maa_v, maa_r, maa_g, xw, xk, xv, xr, xg);
    }

    dim3 gtc(6, NR / 128);
    gemm_tf32_kernel<0><<<gtc, 256, GT_SMEM>>>(xr, Wr_c, rb, CDIM, CDIM, nullptr);
    gemm_tf32_kernel<0><<<gtc, 256, GT_SMEM>>>(xk, Wk_c, kb, CDIM, CDIM, nullptr);
    gemm_tf32_kernel<0><<<gtc, 256, GT_SMEM>>>(xv, Wv_c, vb, CDIM, CDIM, nullptr);
    gemm_tf32_kernel<2><<<gtc, 256, GT_SMEM>>>(xg, Wg_c, gb, CDIM, CDIM, nullptr);

    // h1 = tanh(xw @ dec_w1)  [NR,64] (rounded in epilogue)
    {
        dim3 grid(1, NR / 128);
        gemm_tf32_kernel<4><<<grid, 256, GT_SMEM>>>(xw, D1t, h1, 64, CDIM, nullptr);
    }
    // w = time_decay + h1 @ dec_w2  [NR,768]
    gemm_tf32_kernel<3><<<gtc, 256, GT_SMEM>>>(h1, D2t, wb, CDIM, 64, time_decay);

    // WKV6
    wkv6_kernel<<<8 * NHEAD, 256>>>(rb, kb, vb, wb, faaaa, yb);

    // GroupNorm * g
    gn_mul_kernel<<<NR, 384>>>(yb, ln_w, ln_b, gb, yg);

    // out = yg @ W_o.T
    gemm_tf32_kernel<0><<<gtc, 256, GT_SMEM>>>(yg, Wo_c, out, CDIM, CDIM, nullptr);
}

// round 8
// speedup vs baseline: 1.2008x; 1.0253x over previous
#include <cuda_runtime.h>
#include <math.h>

#define TDIM 1024
#define CDIM 768
#define PH 32
#define PW 32
#define NHEAD 12
#define HS 64
#define NR (8*1024)

__device__ float g_xx [NR*CDIM];
__device__ float g_xxx[NR*CDIM];
__device__ float g_t  [NR*160];
__device__ float g_xw [NR*CDIM];
__device__ float g_xk [NR*CDIM];
__device__ float g_xv [NR*CDIM];
__device__ float g_xr [NR*CDIM];
__device__ float g_xg [NR*CDIM];
__device__ float g_r  [NR*CDIM];
__device__ float g_k  [NR*CDIM];
__device__ float g_v  [NR*CDIM];
__device__ float g_g  [NR*CDIM];
__device__ float g_h1 [NR*64];
__device__ float g_w  [NR*CDIM];
__device__ float g_y  [NR*CDIM];
__device__ float g_yg [NR*CDIM];
__device__ float g_Wc [5*CDIM*CDIM];
__device__ float g_Wt [160*CDIM + 64*CDIM + CDIM*64];

__device__ __forceinline__ float tf32r(float x) {
    unsigned u;
    asm("cvt.rna.tf32.f32 %0, %1;" : "=r"(u) : "f"(x));
    return __uint_as_float(u);
}
__device__ __forceinline__ void cp16(void* dst, const void* src) {
    unsigned d = (unsigned)__cvta_generic_to_shared(dst);
    asm volatile("cp.async.cg.shared.global [%0], [%1], 16;" :: "r"(d), "l"(src) : "memory");
}
__device__ __forceinline__ void cp16z(void* dst, const void* src, int sz) {
    unsigned d = (unsigned)__cvta_generic_to_shared(dst);
    asm volatile("cp.async.cg.shared.global [%0], [%1], 16, %2;" :: "r"(d), "l"(src), "r"(sz) : "memory");
}

// ---------------- weight prep ----------------
__global__ void round_w_kernel(const float* __restrict__ w0, const float* __restrict__ w1,
                               const float* __restrict__ w2, const float* __restrict__ w3,
                               const float* __restrict__ w4, float* __restrict__ out)
{
    int idx = blockIdx.x * blockDim.x + threadIdx.x;
    const int NW = CDIM * CDIM;
    if (idx >= 5 * NW) return;
    int m = idx / NW, r = idx % NW;
    const float* src = (m == 0) ? w0 : (m == 1) ? w1 : (m == 2) ? w2 : (m == 3) ? w3 : w4;
    out[idx] = tf32r(src[r]);
}
__global__ void transpose_round_kernel(const float* __restrict__ in, float* __restrict__ out,
                                       int R, int Ccols)
{
    int idx = blockIdx.x * blockDim.x + threadIdx.x;
    if (idx >= R * Ccols) return;
    int r = idx / Ccols, c = idx % Ccols;
    out[c * R + r] = tf32r(in[idx]);
}

// ---------------- K1: q_shift + maa_x mix ----------------
__global__ void shift_mix_kernel(const float* __restrict__ x,
                                 const float* __restrict__ maa_x,
                                 float* __restrict__ xx, float* __restrict__ xxx,
                                 int total)
{
    int idx = blockIdx.x * blockDim.x + threadIdx.x;
    if (idx >= total) return;
    int c = idx % CDIM;
    int t = (idx / CDIM) % TDIM;
    int b = idx / (CDIM * TDIM);
    int d  = c & (HS - 1);
    int hh = t >> 5, ww = t & 31;
    float sh = 0.f;
    int st = -1;
    if (d < 16)      { if (ww >= 1)      st = t - 1;  }
    else if (d < 32) { if (ww < PW - 1)  st = t + 1;  }
    else if (d < 48) { if (hh >= 1)      st = t - PW; }
    else             { if (hh < PH - 1)  st = t + PW; }
    if (st >= 0) sh = x[((size_t)b * TDIM + st) * CDIM + c];
    float xv = x[idx];
    float dd = sh - xv;
    xx[idx]  = dd;
    xxx[idx] = tf32r(xv + dd * maa_x[c]);
}

// ---------------- mma.sync tf32 GEMM ----------------
#define ASTR   36
#define ASZ    (128*ASTR)
#define GT_SMEM (4*ASZ*4)

template<int EPI>
__device__ __forceinline__ float epi_f(float a, const float* bias, int n) {
    if (EPI == 1) return tanhf(a);
    if (EPI == 2) return fmaxf(a, 0.f);
    if (EPI == 3) return a + bias[n];
    if (EPI == 4) return tf32r(tanhf(a));
    return a;
}

__device__ __forceinline__ void gt_issue(float* sm, const float* __restrict__ A,
                                         const float* __restrict__ Bm,
                                         int m0, int n0, int it, int tid, int N, int K)
{
    int s = it & 1;
    float* As = sm + s * ASZ;
    float* Bs = sm + 2 * ASZ + s * ASZ;
    int k0 = it * 32;
#pragma unroll
    for (int p = 0; p < 4; p++) {
        int c = tid + p * 256;
        int row = c >> 3, kc = (c & 7) << 2;
        cp16(As + row * ASTR + kc, A + (size_t)(m0 + row) * K + k0 + kc);
    }
#pragma unroll
    for (int p = 0; p < 4; p++) {
        int c = tid + p * 256;
        int row = c >> 3, kc = (c & 7) << 2;
        int valid = (n0 + row) < N;
        const float* src = Bm + (valid ? ((size_t)(n0 + row) * K + k0 + kc) : 0);
        cp16z(Bs + row * ASTR + kc, src, valid ? 16 : 0);
    }
    asm volatile("cp.async.commit_group;" ::: "memory");
}

// shared compute body: accumulates over K, then writes epilogue
template<int EPI, bool RELU_RT>
__device__ __forceinline__ void gt_body(const float* __restrict__ A, const float* __restrict__ Bm,
                                        float* __restrict__ Cm, int N, int K,
                                        const float* __restrict__ bias, int relu_flag)
{
    extern __shared__ __align__(16) float sm[];
    int tid = threadIdx.x;
    int lane = tid & 31, warp = tid >> 5;
    int warp_m = warp >> 2, warp_n = warp & 3;
    int m0 = blockIdx.y * 128, n0 = blockIdx.x * 128;

    int lrow = lane & 7;
    int a_m = ((lane >> 3) & 1) * 8 + lrow;
    int a_k = (lane >> 4) * 4;
    int b_k = ((lane >> 3) & 1) * 4;

    float acc[4][4][4];
#pragma unroll
    for (int i = 0; i < 4; i++)
#pragma unroll
        for (int j = 0; j < 4; j++)
#pragma unroll
            for (int q = 0; q < 4; q++) acc[i][j][q] = 0.f;

    gt_issue(sm, A, Bm, m0, n0, 0, tid, N, K);

    const int NIT = K / 32;
#pragma unroll 1
    for (int it = 0; it < NIT; it++) {
        if (it + 1 < NIT) {
            gt_issue(sm, A, Bm, m0, n0, it + 1, tid, N, K);
            asm volatile("cp.async.wait_group 1;" ::: "memory");
        } else {
            asm volatile("cp.async.wait_group 0;" ::: "memory");
        }
        __syncthreads();
        int s = it & 1;
        const float* As = sm + s * ASZ;
        const float* Bs = sm + 2 * ASZ + s * ASZ;
#pragma unroll
        for (int ks = 0; ks < 4; ks++) {
            unsigned af[4][4], bf[4][2];
#pragma unroll
            for (int mi = 0; mi < 4; mi++) {
                const float* p = As + (warp_m * 64 + mi * 16 + a_m) * ASTR + ks * 8 + a_k;
                unsigned ad = (unsigned)__cvta_generic_to_shared(p);
                asm volatile("ldmatrix.sync.aligned.m8n8.x4.shared.b16 {%0,%1,%2,%3}, [%4];"
                    : "=r"(af[mi][0]), "=r"(af[mi][1]), "=r"(af[mi][2]), "=r"(af[mi][3]) : "r"(ad));
            }
#pragma unroll
            for (int ni = 0; ni < 4; ni++) {
                const float* p = Bs + (warp_n * 32 + ni * 8 + lrow) * ASTR + ks * 8 + b_k;
                unsigned ad = (unsigned)__cvta_generic_to_shared(p);
                asm volatile("ldmatrix.sync.aligned.m8n8.x2.shared.b16 {%0,%1}, [%2];"
                    : "=r"(bf[ni][0]), "=r"(bf[ni][1]) : "r"(ad));
            }
#pragma unroll
            for (int mi = 0; mi < 4; mi++)
#pragma unroll
                for (int ni = 0; ni < 4; ni++) {
                    asm volatile(
                        "mma.sync.aligned.m16n8k8.row.col.f32.tf32.tf32.f32 "
                        "{%0,%1,%2,%3}, {%4,%5,%6,%7}, {%8,%9}, {%0,%1,%2,%3};"
                        : "+f"(acc[mi][ni][0]), "+f"(acc[mi][ni][1]),
                          "+f"(acc[mi][ni][2]), "+f"(acc[mi][ni][3])
                        : "r"(af[mi][0]), "r"(af[mi][1]), "r"(af[mi][2]), "r"(af[mi][3]),
                          "r"(bf[ni][0]), "r"(bf[ni][1]));
                }
        }
        __syncthreads();
    }

    int erow = lane >> 2, ecol = (lane & 3) * 2;
#pragma unroll
    for (int mi = 0; mi < 4; mi++) {
#pragma unroll
        for (int ni = 0; ni < 4; ni++) {
            int m = m0 + warp_m * 64 + mi * 16 + erow;
            int n = n0 + warp_n * 32 + ni * 8 + ecol;
            if (n < N) {
                float2 v0, v1;
                v0.x = epi_f<EPI>(acc[mi][ni][0], bias, n);
                v0.y = epi_f<EPI>(acc[mi][ni][1], bias, n + 1);
                v1.x = epi_f<EPI>(acc[mi][ni][2], bias, n);
                v1.y = epi_f<EPI>(acc[mi][ni][3], bias, n + 1);
                if (RELU_RT && relu_flag) {
                    v0.x = fmaxf(v0.x, 0.f); v0.y = fmaxf(v0.y, 0.f);
                    v1.x = fmaxf(v1.x, 0.f); v1.y = fmaxf(v1.y, 0.f);
                }
                *(float2*)(Cm + (size_t)m * N + n) = v0;
                *(float2*)(Cm + (size_t)(m + 8) * N + n) = v1;
            }
        }
    }
}

template<int EPI>
__global__ __launch_bounds__(256, 2) void gemm_tf32_kernel(
    const float* __restrict__ A, const float* __restrict__ Bm,
    float* __restrict__ Cm, int N, int K, const float* __restrict__ bias)
{
    gt_body<EPI, false>(A, Bm, Cm, N, K, bias, 0);
}

// batched over z: 4 independent GEMMs (r,k,v,g); z==3 applies relu
__global__ __launch_bounds__(256, 2) void gemm_tf32_qkvg_kernel(
    const float* __restrict__ a0, const float* __restrict__ a1,
    const float* __restrict__ a2, const float* __restrict__ a3,
    const float* __restrict__ b0, const float* __restrict__ b1,
    const float* __restrict__ b2, const float* __restrict__ b3,
    float* __restrict__ c0, float* __restrict__ c1,
    float* __restrict__ c2, float* __restrict__ c3)
{
    int z = blockIdx.z;
    const float* A  = (z == 0) ? a0 : (z == 1) ? a1 : (z == 2) ? a2 : a3;
    const float* Bm = (z == 0) ? b0 : (z == 1) ? b1 : (z == 2) ? b2 : b3;
    float* Cm       = (z == 0) ? c0 : (z == 1) ? c1 : (z == 2) ? c2 : c3;
    gt_body<0, true>(A, Bm, Cm, CDIM, CDIM, nullptr, z == 3);
}

// ---------------- K3: 5-way token-shift mixer ----------------
#define MIX5_SMEM ((160*64 + 8*160) * 4)
__global__ __launch_bounds__(256) void mix5_kernel(
    const float* __restrict__ x, const float* __restrict__ xx,
    const float* __restrict__ t_arr, const float* __restrict__ w2,
    const float* __restrict__ mw, const float* __restrict__ mk,
    const float* __restrict__ mv, const float* __restrict__ mr,
    const float* __restrict__ mg,
    float* __restrict__ xw, float* __restrict__ xk, float* __restrict__ xv,
    float* __restrict__ xr, float* __restrict__ xg)
{
    extern __shared__ __align__(16) float sm[];
    float* w2s = sm;
    float* ts2 = sm + 160 * 64;
    int tid = threadIdx.x;
    int c0 = blockIdx.x * 64;
    int rbase = blockIdx.y * 64;
    int c = tid & 63, rr = tid >> 6;

    for (int i = tid; i < 160 * 64; i += 256)
        w2s[i] = w2[(i >> 6) * CDIM + c0 + (i & 63)];
    float cw = mw[c0 + c], ck = mk[c0 + c], cv = mv[c0 + c],
          cr = mr[c0 + c], cg = mg[c0 + c];
    __syncthreads();

#pragma unroll 1
    for (int grp = 0; grp < 8; grp++) {
        int row0 = rbase + grp * 8;
        for (int i = tid; i < 8 * 160; i += 256)
            ts2[i] = t_arr[(size_t)(row0 + i / 160) * 160 + (i % 160)];
        __syncthreads();

        float acc[2][5];
#pragma unroll
        for (int r = 0; r < 2; r++)
#pragma unroll
            for (int f = 0; f < 5; f++) acc[r][f] = 0.f;

#pragma unroll
        for (int f = 0; f < 5; f++) {
#pragma unroll
            for (int j4 = 0; j4 < 8; j4++) {
                int jb = f * 32 + j4 * 4;
                float w0 = w2s[(jb + 0) * 64 + c];
                float w1 = w2s[(jb + 1) * 64 + c];
                float w2v = w2s[(jb + 2) * 64 + c];
                float w3 = w2s[(jb + 3) * 64 + c];
#pragma unroll
                for (int r = 0; r < 2; r++) {
                    float4 tv = *(const float4*)&ts2[(rr * 2 + r) * 160 + jb];
                    acc[r][f] += tv.x * w0 + tv.y * w1 + tv.z * w2v + tv.w * w3;
                }
            }
        }
#pragma unroll
        for (int r = 0; r < 2; r++) {
            size_t gi = (size_t)(row0 + rr * 2 + r) * CDIM + c0 + c;
            float xval = x[gi], xxval = xx[gi];
            xw[gi] = tf32r(xval + xxval * (cw + acc[r][0]));
            xk[gi] = tf32r(xval + xxval * (ck + acc[r][1]));
            xv[gi] = tf32r(xval + xxval * (cv + acc[r][2]));
            xr[gi] = tf32r(xval + xxval * (cr + acc[r][3]));
            xg[gi] = tf32r(xval + xxval * (cg + acc[r][4]));
        }
        __syncthreads();
    }
}

// ---------------- K4: WKV6 recurrence ----------------
__device__ __forceinline__ void wkv_issue(int ci, float* rsb, float* ksb,
        float* vsb, float* wsb,
        const float* rp, const float* kp, const float* vp, const float* wpp,
        size_t base, int tid)
{
#pragma unroll
    for (int p = 0; p < 2; p++) {
        int idx = tid + p * 256;
        int arr = idx >> 7;
        int rem = idx & 127;
        int tc = rem >> 4, c4 = (rem & 15) << 2;
        size_t gofs = base + (size_t)(ci * 8 + tc) * CDIM + c4;
        float* dst; const float* src;
        if (arr == 0)      { dst = rsb + tc * 64 + c4; src = rp  + gofs; }
        else if (arr == 1) { dst = ksb + tc * 64 + c4; src = kp  + gofs; }
        else if (arr == 2) { dst = vsb + tc * 64 + c4; src = vp  + gofs; }
        else               { dst = wsb + tc * 64 + c4; src = wpp + gofs; }
        cp16(dst, src);
    }
    asm volatile("cp.async.commit_group;" ::: "memory");
}

__global__ __launch_bounds__(256, 1) void wkv6_kernel(
    const float* __restrict__ rp, const float* __restrict__ kp,
    const float* __restrict__ vp, const float* __restrict__ wp_,
    const float* __restrict__ up, float* __restrict__ yp)
{
    __shared__ __align__(16) float rs[2][512], ks[2][512], vs[2][512], ws[2][512];
    __shared__ float us[64], ruks[8];
    int tid = threadIdx.x;
    int b = blockIdx.x / NHEAD, h = blockIdx.x % NHEAD;
    size_t base = (size_t)b * TDIM * CDIM + h * HS;
    if (tid < 64) us[tid] = up[h * HS + tid];
    int i = tid >> 2, jq = tid & 3;
    int lane = tid & 31, warp = tid >> 5;

    float S[16];
#pragma unroll
    for (int q = 0; q < 16; q++) S[q] = 0.f;

    wkv_issue(0, rs[0], ks[0], vs[0], ws[0], rp, kp, vp, wp_, base, tid);

#pragma unroll 1
    for (int ci = 0; ci < TDIM / 8; ci++) {
        int buf = ci & 1;
        asm volatile("cp.async.wait_group 0;" ::: "memory");
        __syncthreads();
        for (int idx = tid; idx < 512; idx += 256)
            ws[buf][idx] = expf(-expf(ws[buf][idx]));
        {
            float p = rs[buf][warp * 64 + lane] * us[lane] * ks[buf][warp * 64 + lane]
                    + rs[buf][warp * 64 + 32 + lane] * us[32 + lane] * ks[buf][warp * 64 + 32 + lane];
#pragma unroll
            for (int o = 16; o; o >>= 1) p += __shfl_xor_sync(0xffffffffu, p, o);
            if (lane == 0) ruks[warp] = p;
        }
        __syncthreads();
        if (ci + 1 < TDIM / 8) {
            int nb = buf ^ 1;
            wkv_issue(ci + 1, rs[nb], ks[nb], vs[nb], ws[nb], rp, kp, vp, wp_, base, tid);
        }
#pragma unroll 1
        for (int tc = 0; tc < 8; tc++) {
            float vi = vs[buf][tc * 64 + i];
            const float4* r4 = (const float4*)&rs[buf][tc * 64 + jq * 16];
            const float4* k4 = (const float4*)&ks[buf][tc * 64 + jq * 16];
            const float4* w4 = (const float4*)&ws[buf][tc * 64 + jq * 16];
            float yps = 0.f;
#pragma unroll
            for (int q = 0; q < 4; q++) {
                float4 rv = r4[q], kv = k4[q], wv = w4[q];
                yps += rv.x * S[q * 4 + 0]; S[q * 4 + 0] = wv.x * S[q * 4 + 0] + kv.x * vi;
                yps += rv.y * S[q * 4 + 1]; S[q * 4 + 1] = wv.y * S[q * 4 + 1] + kv.y * vi;
                yps += rv.z * S[q * 4 + 2]; S[q * 4 + 2] = wv.z * S[q * 4 + 2] + kv.z * vi;
                yps += rv.w * S[q * 4 + 3]; S[q * 4 + 3] = wv.w * S[q * 4 + 3] + kv.w * vi;
            }
            yps += __shfl_xor_sync(0xffffffffu, yps, 1);
            yps += __shfl_xor_sync(0xffffffffu, yps, 2);
            if (jq == 0)
                yp[base + (size_t)(ci * 8 + tc) * CDIM + i] = yps + vi * ruks[tc];
        }
    }
}

// ---------------- K5: per-head GroupNorm * g ----------------
__global__ void gn_mul_kernel(const float* __restrict__ y,
                              const float* __restrict__ lw, const float* __restrict__ lb,
                              const float* __restrict__ g, float* __restrict__ out)
{
    int row = blockIdx.x;
    int warp = threadIdx.x >> 5, lane = threadIdx.x & 31;
    size_t o = (size_t)row * CDIM + warp * HS;
    float v0 = y[o + lane], v1 = y[o + 32 + lane];
    float s = v0 + v1, ss = v0 * v0 + v1 * v1;
#pragma unroll
    for (int off = 16; off; off >>= 1) {
        s  += __shfl_xor_sync(0xffffffffu, s,  off);
        ss += __shfl_xor_sync(0xffffffffu, ss, off);
    }
    float mean = s * (1.f / HS);
    float var  = ss * (1.f / HS) - mean * mean;
    float inv  = rsqrtf(var + 1e-5f);
    int c0 = warp * HS + lane, c1 = c0 + 32;
    float n0 = (v0 - mean) * inv * lw[c0] + lb[c0];
    float n1 = (v1 - mean) * inv * lw[c1] + lb[c1];
    out[o + lane]      = tf32r(n0 * g[o + lane]);
    out[o + 32 + lane] = tf32r(n1 * g[o + 32 + lane]);
}

// ---------------- launcher ----------------
extern "C" void kernel_launch(void* const* d_in, const int* in_sizes, int n_in,
                              void* d_out, int out_size)
{
    const float* x          = (const float*)d_in[0];
    const float* W_r        = (const float*)d_in[1];
    const float* W_k        = (const float*)d_in[2];
    const float* W_v        = (const float*)d_in[3];
    const float* W_g        = (const float*)d_in[4];
    const float* W_o        = (const float*)d_in[5];
    const float* maa_x      = (const float*)d_in[6];
    const float* maa_w      = (const float*)d_in[7];
    const float* maa_k      = (const float*)d_in[8];
    const float* maa_v      = (const float*)d_in[9];
    const float* maa_r      = (const float*)d_in[10];
    const float* maa_g      = (const float*)d_in[11];
    const float* maa_w1     = (const float*)d_in[12];
    const float* maa_w2     = (const float*)d_in[13];
    const float* time_decay = (const float*)d_in[14];
    const float* dec_w1     = (const float*)d_in[15];
    const float* dec_w2     = (const float*)d_in[16];
    const float* faaaa      = (const float*)d_in[17];
    const float* ln_w       = (const float*)d_in[18];
    const float* ln_b       = (const float*)d_in[19];
    float* out = (float*)d_out;

    float *xx, *xxx, *tb, *xw, *xk, *xv, *xr, *xg, *rb, *kb, *vb, *gb, *h1, *wb, *yb, *yg, *Wc, *Wt;
    cudaGetSymbolAddress((void**)&xx,  g_xx);
    cudaGetSymbolAddress((void**)&xxx, g_xxx);
    cudaGetSymbolAddress((void**)&tb,  g_t);
    cudaGetSymbolAddress((void**)&xw,  g_xw);
    cudaGetSymbolAddress((void**)&xk,  g_xk);
    cudaGetSymbolAddress((void**)&xv,  g_xv);
    cudaGetSymbolAddress((void**)&xr,  g_xr);
    cudaGetSymbolAddress((void**)&xg,  g_xg);
    cudaGetSymbolAddress((void**)&rb,  g_r);
    cudaGetSymbolAddress((void**)&kb,  g_k);
    cudaGetSymbolAddress((void**)&vb,  g_v);
    cudaGetSymbolAddress((void**)&gb,  g_g);
    cudaGetSymbolAddress((void**)&h1,  g_h1);
    cudaGetSymbolAddress((void**)&wb,  g_w);
    cudaGetSymbolAddress((void**)&yb,  g_y);
    cudaGetSymbolAddress((void**)&yg,  g_yg);
    cudaGetSymbolAddress((void**)&Wc,  g_Wc);
    cudaGetSymbolAddress((void**)&Wt,  g_Wt);

    const int NW = CDIM * CDIM;
    float* Wr_c = Wc + 0 * NW;
    float* Wk_c = Wc + 1 * NW;
    float* Wv_c = Wc + 2 * NW;
    float* Wg_c = Wc + 3 * NW;
    float* Wo_c = Wc + 4 * NW;
    float* W1t  = Wt;
    float* D1t  = Wt + 160 * CDIM;
    float* D2t  = Wt + 160 * CDIM + 64 * CDIM;

    cudaFuncSetAttribute(mix5_kernel, cudaFuncAttributeMaxDynamicSharedMemorySize, MIX5_SMEM);
    cudaFuncSetAttribute(gemm_tf32_kernel<0>, cudaFuncAttributeMaxDynamicSharedMemorySize, GT_SMEM);
    cudaFuncSetAttribute(gemm_tf32_kernel<1>, cudaFuncAttributeMaxDynamicSharedMemorySize, GT_SMEM);
    cudaFuncSetAttribute(gemm_tf32_kernel<3>, cudaFuncAttributeMaxDynamicSharedMemorySize, GT_SMEM);
    cudaFuncSetAttribute(gemm_tf32_kernel<4>, cudaFuncAttributeMaxDynamicSharedMemorySize, GT_SMEM);
    cudaFuncSetAttribute(gemm_tf32_qkvg_kernel, cudaFuncAttributeMaxDynamicSharedMemorySize, GT_SMEM);

    int total = NR * CDIM;

    // Launch order arranged so ncu (-s 5 -c 1) captures the batched big GEMM (#6).
    transpose_round_kernel<<<(CDIM * 160 + 255) / 256, 256>>>(maa_w1, W1t, CDIM, 160);   // 1
    shift_mix_kernel<<<(total + 255) / 256, 256>>>(x, maa_x, xx, xxx, total);            // 2
    {                                                                                     // 3
        dim3 grid(2, NR / 128);
        gemm_tf32_kernel<1><<<grid, 256, GT_SMEM>>>(xxx, W1t, tb, 160, CDIM, nullptr);
    }
    {                                                                                     // 4
        dim3 grid(CDIM / 64, NR / 64);
        mix5_kernel<<<grid, 256, MIX5_SMEM>>>(x, xx, tb, maa_w2,
            maa_w, maa_k, maa_v, maa_r, maa_g, xw, xk, xv, xr, xg);
    }
    round_w_kernel<<<(5 * NW + 255) / 256, 256>>>(W_r, W_k, W_v, W_g, W_o, Wc);          // 5
    {                                                                                     // 6 <- profiled
        dim3 grid(6, NR / 128, 4);
        gemm_tf32_qkvg_kernel<<<grid, 256, GT_SMEM>>>(
            xr, xk, xv, xg, Wr_c, Wk_c, Wv_c, Wg_c, rb, kb, vb, gb);
    }
    transpose_round_kernel<<<(CDIM * 64 + 255) / 256, 256>>>(dec_w1, D1t, CDIM, 64);
    transpose_round_kernel<<<(64 * CDIM + 255) / 256, 256>>>(dec_w2, D2t, 64, CDIM);
    {
        dim3 grid(1, NR / 128);
        gemm_tf32_kernel<4><<<grid, 256, GT_SMEM>>>(xw, D1t, h1, 64, CDIM, nullptr);
    }
    {
        dim3 gcc(6, NR / 128);
        gemm_tf32_kernel<3><<<gcc, 256, GT_SMEM>>>(h1, D2t, wb, CDIM, 64, time_decay);
    }
    wkv6_kernel<<<8 * NHEAD, 256>>>(rb, kb, vb, wb, faaaa, yb);
    gn_mul_kernel<<<NR, 384>>>(yb, ln_w, ln_b, gb, yg);
    {
        dim3 gcc(6, NR / 128);
        gemm_tf32_kernel<0><<<gcc, 256, GT_SMEM>>>(yg, Wo_c, out, CDIM, CDIM, nullptr);
    }
}

// round 9
// speedup vs baseline: 1.2845x; 1.0697x over previous
#include <cuda_runtime.h>
#include <math.h>

#define TDIM 1024
#define CDIM 768
#define PH 32
#define PW 32
#define NHEAD 12
#define HS 64
#define NR (8*1024)

__device__ float g_xx [NR*CDIM];
__device__ float g_xxx[NR*CDIM];
__device__ float g_t  [NR*160];
__device__ float g_xw [NR*CDIM];
__device__ float g_xk [NR*CDIM];
__device__ float g_xv [NR*CDIM];
__device__ float g_xr [NR*CDIM];
__device__ float g_xg [NR*CDIM];
__device__ float g_r  [NR*CDIM];
__device__ float g_k  [NR*CDIM];
__device__ float g_v  [NR*CDIM];
__device__ float g_g  [NR*CDIM];
__device__ float g_h1 [NR*64];
__device__ float g_w  [NR*CDIM];
__device__ float g_y  [NR*CDIM];
__device__ float g_yg [NR*CDIM];
__device__ float g_Wc [5*CDIM*CDIM];
__device__ float g_Wt [160*CDIM + 64*CDIM + CDIM*64];
__device__ float g_Wm [5*CDIM*32];     // mix-w2 transposed per f: [f][c][j]

__device__ __forceinline__ float tf32r(float x) {
    unsigned u;
    asm("cvt.rna.tf32.f32 %0, %1;" : "=r"(u) : "f"(x));
    return __uint_as_float(u);
}
__device__ __forceinline__ void cp16(void* dst, const void* src) {
    unsigned d = (unsigned)__cvta_generic_to_shared(dst);
    asm volatile("cp.async.cg.shared.global [%0], [%1], 16;" :: "r"(d), "l"(src) : "memory");
}
__device__ __forceinline__ void cp16z(void* dst, const void* src, int sz) {
    unsigned d = (unsigned)__cvta_generic_to_shared(dst);
    asm volatile("cp.async.cg.shared.global [%0], [%1], 16, %2;" :: "r"(d), "l"(src), "r"(sz) : "memory");
}

// ---------------- weight prep ----------------
__global__ void round_w_kernel(const float* __restrict__ w0, const float* __restrict__ w1,
                               const float* __restrict__ w2, const float* __restrict__ w3,
                               const float* __restrict__ w4, float* __restrict__ out)
{
    int idx = blockIdx.x * blockDim.x + threadIdx.x;
    const int NW = CDIM * CDIM;
    if (idx >= 5 * NW) return;
    int m = idx / NW, r = idx % NW;
    const float* src = (m == 0) ? w0 : (m == 1) ? w1 : (m == 2) ? w2 : (m == 3) ? w3 : w4;
    out[idx] = tf32r(src[r]);
}
__global__ void transpose_round_kernel(const float* __restrict__ in, float* __restrict__ out,
                                       int R, int Ccols)
{
    int idx = blockIdx.x * blockDim.x + threadIdx.x;
    if (idx >= R * Ccols) return;
    int r = idx / Ccols, c = idx % Ccols;
    out[c * R + r] = tf32r(in[idx]);
}
// maa_w2 [5*32, CDIM] -> Wm [f][c][j]
__global__ void mixw2_prep_kernel(const float* __restrict__ w2, float* __restrict__ out)
{
    int idx = blockIdx.x * blockDim.x + threadIdx.x;
    if (idx >= 5 * CDIM * 32) return;
    int f = idx / (CDIM * 32);
    int rem = idx % (CDIM * 32);
    int c = rem >> 5, j = rem & 31;
    out[idx] = tf32r(w2[(f * 32 + j) * CDIM + c]);
}

// ---------------- K1: q_shift + maa_x mix ----------------
__global__ void shift_mix_kernel(const float* __restrict__ x,
                                 const float* __restrict__ maa_x,
                                 float* __restrict__ xx, float* __restrict__ xxx,
                                 int total)
{
    int idx = blockIdx.x * blockDim.x + threadIdx.x;
    if (idx >= total) return;
    int c = idx % CDIM;
    int t = (idx / CDIM) % TDIM;
    int b = idx / (CDIM * TDIM);
    int d  = c & (HS - 1);
    int hh = t >> 5, ww = t & 31;
    float sh = 0.f;
    int st = -1;
    if (d < 16)      { if (ww >= 1)      st = t - 1;  }
    else if (d < 32) { if (ww < PW - 1)  st = t + 1;  }
    else if (d < 48) { if (hh >= 1)      st = t - PW; }
    else             { if (hh < PH - 1)  st = t + PW; }
    if (st >= 0) sh = x[((size_t)b * TDIM + st) * CDIM + c];
    float xv = x[idx];
    float dd = sh - xv;
    xx[idx]  = dd;
    xxx[idx] = tf32r(xv + dd * maa_x[c]);
}

// ---------------- mma.sync tf32 GEMM ----------------
#define ASTR   36
#define ASZ    (128*ASTR)
#define GT_SMEM (4*ASZ*4)

template<int EPI>
__device__ __forceinline__ float epi_f(float a, const float* bias, int n) {
    if (EPI == 1) return tanhf(a);
    if (EPI == 2) return fmaxf(a, 0.f);
    if (EPI == 3) return a + bias[n];
    if (EPI == 4) return tf32r(tanhf(a));
    return a;
}

__device__ __forceinline__ void gt_issue(float* sm, const float* __restrict__ A,
                                         const float* __restrict__ Bm,
                                         int m0, int n0, int it, int tid, int N, int K)
{
    int s = it & 1;
    float* As = sm + s * ASZ;
    float* Bs = sm + 2 * ASZ + s * ASZ;
    int k0 = it * 32;
#pragma unroll
    for (int p = 0; p < 4; p++) {
        int c = tid + p * 256;
        int row = c >> 3, kc = (c & 7) << 2;
        cp16(As + row * ASTR + kc, A + (size_t)(m0 + row) * K + k0 + kc);
    }
#pragma unroll
    for (int p = 0; p < 4; p++) {
        int c = tid + p * 256;
        int row = c >> 3, kc = (c & 7) << 2;
        int valid = (n0 + row) < N;
        const float* src = Bm + (valid ? ((size_t)(n0 + row) * K + k0 + kc) : 0);
        cp16z(Bs + row * ASTR + kc, src, valid ? 16 : 0);
    }
    asm volatile("cp.async.commit_group;" ::: "memory");
}

template<int EPI, bool RELU_RT>
__device__ __forceinline__ void gt_body(const float* __restrict__ A, const float* __restrict__ Bm,
                                        float* __restrict__ Cm, int N, int K,
                                        const float* __restrict__ bias, int relu_flag)
{
    extern __shared__ __align__(16) float sm[];
    int tid = threadIdx.x;
    int lane = tid & 31, warp = tid >> 5;
    int warp_m = warp >> 2, warp_n = warp & 3;
    int m0 = blockIdx.y * 128, n0 = blockIdx.x * 128;

    int lrow = lane & 7;
    int a_m = ((lane >> 3) & 1) * 8 + lrow;
    int a_k = (lane >> 4) * 4;
    int b_k = ((lane >> 3) & 1) * 4;

    float acc[4][4][4];
#pragma unroll
    for (int i = 0; i < 4; i++)
#pragma unroll
        for (int j = 0; j < 4; j++)
#pragma unroll
            for (int q = 0; q < 4; q++) acc[i][j][q] = 0.f;

    gt_issue(sm, A, Bm, m0, n0, 0, tid, N, K);

    const int NIT = K / 32;
#pragma unroll 1
    for (int it = 0; it < NIT; it++) {
        if (it + 1 < NIT) {
            gt_issue(sm, A, Bm, m0, n0, it + 1, tid, N, K);
            asm volatile("cp.async.wait_group 1;" ::: "memory");
        } else {
            asm volatile("cp.async.wait_group 0;" ::: "memory");
        }
        __syncthreads();
        int s = it & 1;
        const float* As = sm + s * ASZ;
        const float* Bs = sm + 2 * ASZ + s * ASZ;
#pragma unroll
        for (int ks = 0; ks < 4; ks++) {
            unsigned af[4][4], bf[4][2];
#pragma unroll
            for (int mi = 0; mi < 4; mi++) {
                const float* p = As + (warp_m * 64 + mi * 16 + a_m) * ASTR + ks * 8 + a_k;
                unsigned ad = (unsigned)__cvta_generic_to_shared(p);
                asm volatile("ldmatrix.sync.aligned.m8n8.x4.shared.b16 {%0,%1,%2,%3}, [%4];"
                    : "=r"(af[mi][0]), "=r"(af[mi][1]), "=r"(af[mi][2]), "=r"(af[mi][3]) : "r"(ad));
            }
#pragma unroll
            for (int ni = 0; ni < 4; ni++) {
                const float* p = Bs + (warp_n * 32 + ni * 8 + lrow) * ASTR + ks * 8 + b_k;
                unsigned ad = (unsigned)__cvta_generic_to_shared(p);
                asm volatile("ldmatrix.sync.aligned.m8n8.x2.shared.b16 {%0,%1}, [%2];"
                    : "=r"(bf[ni][0]), "=r"(bf[ni][1]) : "r"(ad));
            }
#pragma unroll
            for (int mi = 0; mi < 4; mi++)
#pragma unroll
                for (int ni = 0; ni < 4; ni++) {
                    asm volatile(
                        "mma.sync.aligned.m16n8k8.row.col.f32.tf32.tf32.f32 "
                        "{%0,%1,%2,%3}, {%4,%5,%6,%7}, {%8,%9}, {%0,%1,%2,%3};"
                        : "+f"(acc[mi][ni][0]), "+f"(acc[mi][ni][1]),
                          "+f"(acc[mi][ni][2]), "+f"(acc[mi][ni][3])
                        : "r"(af[mi][0]), "r"(af[mi][1]), "r"(af[mi][2]), "r"(af[mi][3]),
                          "r"(bf[ni][0]), "r"(bf[ni][1]));
                }
        }
        __syncthreads();
    }

    int erow = lane >> 2, ecol = (lane & 3) * 2;
#pragma unroll
    for (int mi = 0; mi < 4; mi++) {
#pragma unroll
        for (int ni = 0; ni < 4; ni++) {
            int m = m0 + warp_m * 64 + mi * 16 + erow;
            int n = n0 + warp_n * 32 + ni * 8 + ecol;
            if (n < N) {
                float2 v0, v1;
                v0.x = epi_f<EPI>(acc[mi][ni][0], bias, n);
                v0.y = epi_f<EPI>(acc[mi][ni][1], bias, n + 1);
                v1.x = epi_f<EPI>(acc[mi][ni][2], bias, n);
                v1.y = epi_f<EPI>(acc[mi][ni][3], bias, n + 1);
                if (RELU_RT && relu_flag) {
                    v0.x = fmaxf(v0.x, 0.f); v0.y = fmaxf(v0.y, 0.f);
                    v1.x = fmaxf(v1.x, 0.f); v1.y = fmaxf(v1.y, 0.f);
                }
                *(float2*)(Cm + (size_t)m * N + n) = v0;
                *(float2*)(Cm + (size_t)(m + 8) * N + n) = v1;
            }
        }
    }
}

template<int EPI>
__global__ __launch_bounds__(256, 2) void gemm_tf32_kernel(
    const float* __restrict__ A, const float* __restrict__ Bm,
    float* __restrict__ Cm, int N, int K, const float* __restrict__ bias)
{
    gt_body<EPI, false>(A, Bm, Cm, N, K, bias, 0);
}

__global__ __launch_bounds__(256, 2) void gemm_tf32_qkvg_kernel(
    const float* __restrict__ a0, const float* __restrict__ a1,
    const float* __restrict__ a2, const float* __restrict__ a3,
    const float* __restrict__ b0, const float* __restrict__ b1,
    const float* __restrict__ b2, const float* __restrict__ b3,
    float* __restrict__ c0, float* __restrict__ c1,
    float* __restrict__ c2, float* __restrict__ c3)
{
    int z = blockIdx.z;
    const float* A  = (z == 0) ? a0 : (z == 1) ? a1 : (z == 2) ? a2 : a3;
    const float* Bm = (z == 0) ? b0 : (z == 1) ? b1 : (z == 2) ? b2 : b3;
    float* Cm       = (z == 0) ? c0 : (z == 1) ? c1 : (z == 2) ? c2 : c3;
    gt_body<0, true>(A, Bm, Cm, CDIM, CDIM, nullptr, z == 3);
}

// ---------------- mix5 as GEMM with fused combine epilogue ----------------
// For f=0..4: acc = t[:,f*32:(f+1)*32] @ Wm[f]^T; out_f = tf32r(x + xx*(maa_f + acc))
__device__ __forceinline__ void m5_issue(float* sm, const float* __restrict__ tb,
                                         const float* __restrict__ Wm,
                                         int m0, int n0, int f, int tid)
{
    int s = f & 1;
    float* As = sm + s * ASZ;
    float* Bs = sm + 2 * ASZ + s * ASZ;
#pragma unroll
    for (int p = 0; p < 4; p++) {
        int c = tid + p * 256;
        int row = c >> 3, kc = (c & 7) << 2;
        cp16(As + row * ASTR + kc, tb + (size_t)(m0 + row) * 160 + f * 32 + kc);
        cp16(Bs + row * ASTR + kc, Wm + (size_t)f * CDIM * 32 + (size_t)(n0 + row) * 32 + kc);
    }
    asm volatile("cp.async.commit_group;" ::: "memory");
}

__global__ __launch_bounds__(256, 2) void mix5g_kernel(
    const float* __restrict__ tb, const float* __restrict__ Wm,
    const float* __restrict__ x, const float* __restrict__ xx,
    const float* __restrict__ mw, const float* __restrict__ mk,
    const float* __restrict__ mv, const float* __restrict__ mr,
    const float* __restrict__ mg,
    float* __restrict__ xw, float* __restrict__ xk, float* __restrict__ xv,
    float* __restrict__ xr, float* __restrict__ xg)
{
    extern __shared__ __align__(16) float sm[];
    int tid = threadIdx.x;
    int lane = tid & 31, warp = tid >> 5;
    int warp_m = warp >> 2, warp_n = warp & 3;
    int m0 = blockIdx.y * 128, n0 = blockIdx.x * 128;

    int lrow = lane & 7;
    int a_m = ((lane >> 3) & 1) * 8 + lrow;
    int a_k = (lane >> 4) * 4;
    int b_k = ((lane >> 3) & 1) * 4;
    int erow = lane >> 2, ecol = (lane & 3) * 2;

    m5_issue(sm, tb, Wm, m0, n0, 0, tid);

#pragma unroll 1
    for (int f = 0; f < 5; f++) {
        if (f + 1 < 5) {
            m5_issue(sm, tb, Wm, m0, n0, f + 1, tid);
            asm volatile("cp.async.wait_group 1;" ::: "memory");
        } else {
            asm volatile("cp.async.wait_group 0;" ::: "memory");
        }
        __syncthreads();

        float acc[4][4][4];
#pragma unroll
        for (int i = 0; i < 4; i++)
#pragma unroll
            for (int j = 0; j < 4; j++)
#pragma unroll
                for (int q = 0; q < 4; q++) acc[i][j][q] = 0.f;

        int s = f & 1;
        const float* As = sm + s * ASZ;
        const float* Bs = sm + 2 * ASZ + s * ASZ;
#pragma unroll
        for (int ks = 0; ks < 4; ks++) {
            unsigned af[4][4], bf[4][2];
#pragma unroll
            for (int mi = 0; mi < 4; mi++) {
                const float* p = As + (warp_m * 64 + mi * 16 + a_m) * ASTR + ks * 8 + a_k;
                unsigned ad = (unsigned)__cvta_generic_to_shared(p);
                asm volatile("ldmatrix.sync.aligned.m8n8.x4.shared.b16 {%0,%1,%2,%3}, [%4];"
                    : "=r"(af[mi][0]), "=r"(af[mi][1]), "=r"(af[mi][2]), "=r"(af[mi][3]) : "r"(ad));
            }
#pragma unroll
            for (int ni = 0; ni < 4; ni++) {
                const float* p = Bs + (warp_n * 32 + ni * 8 + lrow) * ASTR + ks * 8 + b_k;
                unsigned ad = (unsigned)__cvta_generic_to_shared(p);
                asm volatile("ldmatrix.sync.aligned.m8n8.x2.shared.b16 {%0,%1}, [%2];"
                    : "=r"(bf[ni][0]), "=r"(bf[ni][1]) : "r"(ad));
            }
#pragma unroll
            for (int mi = 0; mi < 4; mi++)
#pragma unroll
                for (int ni = 0; ni < 4; ni++) {
                    asm volatile(
                        "mma.sync.aligned.m16n8k8.row.col.f32.tf32.tf32.f32 "
                        "{%0,%1,%2,%3}, {%4,%5,%6,%7}, {%8,%9}, {%0,%1,%2,%3};"
                        : "+f"(acc[mi][ni][0]), "+f"(acc[mi][ni][1]),
                          "+f"(acc[mi][ni][2]), "+f"(acc[mi][ni][3])
                        : "r"(af[mi][0]), "r"(af[mi][1]), "r"(af[mi][2]), "r"(af[mi][3]),
                          "r"(bf[ni][0]), "r"(bf[ni][1]));
                }
        }
        __syncthreads();   // stage s fully consumed before it is refilled at f+2

        const float* maa_f = (f == 0) ? mw : (f == 1) ? mk : (f == 2) ? mv : (f == 3) ? mr : mg;
        float* out_f       = (f == 0) ? xw : (f == 1) ? xk : (f == 2) ? xv : (f == 3) ? xr : xg;
#pragma unroll
        for (int mi = 0; mi < 4; mi++) {
#pragma unroll
            for (int ni = 0; ni < 4; ni++) {
                int m = m0 + warp_m * 64 + mi * 16 + erow;
                int n = n0 + warp_n * 32 + ni * 8 + ecol;
                size_t gi0 = (size_t)m * CDIM + n;
                size_t gi1 = (size_t)(m + 8) * CDIM + n;
                float2 xa = *(const float2*)(x + gi0);
                float2 xb = *(const float2*)(x + gi1);
                float2 da = *(const float2*)(xx + gi0);
                float2 db = *(const float2*)(xx + gi1);
                float2 ma = *(const float2*)(maa_f + n);
                float2 v0, v1;
                v0.x = tf32r(xa.x + da.x * (ma.x + acc[mi][ni][0]));
                v0.y = tf32r(xa.y + da.y * (ma.y + acc[mi][ni][1]));
                v1.x = tf32r(xb.x + db.x * (ma.x + acc[mi][ni][2]));
                v1.y = tf32r(xb.y + db.y * (ma.y + acc[mi][ni][3]));
                *(float2*)(out_f + gi0) = v0;
                *(float2*)(out_f + gi1) = v1;
            }
        }
    }
}

// ---------------- K4: WKV6 recurrence ----------------
__device__ __forceinline__ void wkv_issue(int ci, float* rsb, float* ksb,
        float* vsb, float* wsb,
        const float* rp, const float* kp, const float* vp, const float* wpp,
        size_t base, int tid)
{
#pragma unroll
    for (int p = 0; p < 2; p++) {
        int idx = tid + p * 256;
        int arr = idx >> 7;
        int rem = idx & 127;
        int tc = rem >> 4, c4 = (rem & 15) << 2;
        size_t gofs = base + (size_t)(ci * 8 + tc) * CDIM + c4;
        float* dst; const float* src;
        if (arr == 0)      { dst = rsb + tc * 64 + c4; src = rp  + gofs; }
        else if (arr == 1) { dst = ksb + tc * 64 + c4; src = kp  + gofs; }
        else if (arr == 2) { dst = vsb + tc * 64 + c4; src = vp  + gofs; }
        else               { dst = wsb + tc * 64 + c4; src = wpp + gofs; }
        cp16(dst, src);
    }
    asm volatile("cp.async.commit_group;" ::: "memory");
}

__global__ __launch_bounds__(256, 1) void wkv6_kernel(
    const float* __restrict__ rp, const float* __restrict__ kp,
    const float* __restrict__ vp, const float* __restrict__ wp_,
    const float* __restrict__ up, float* __restrict__ yp)
{
    __shared__ __align__(16) float rs[2][512], ks[2][512], vs[2][512], ws[2][512];
    __shared__ float us[64], ruks[8];
    int tid = threadIdx.x;
    int b = blockIdx.x / NHEAD, h = blockIdx.x % NHEAD;
    size_t base = (size_t)b * TDIM * CDIM + h * HS;
    if (tid < 64) us[tid] = up[h * HS + tid];
    int i = tid >> 2, jq = tid & 3;
    int lane = tid & 31, warp = tid >> 5;

    float S[16];
#pragma unroll
    for (int q = 0; q < 16; q++) S[q] = 0.f;

    wkv_issue(0, rs[0], ks[0], vs[0], ws[0], rp, kp, vp, wp_, base, tid);

#pragma unroll 1
    for (int ci = 0; ci < TDIM / 8; ci++) {
        int buf = ci & 1;
        asm volatile("cp.async.wait_group 0;" ::: "memory");
        __syncthreads();
        for (int idx = tid; idx < 512; idx += 256)
            ws[buf][idx] = expf(-expf(ws[buf][idx]));
        {
            float p = rs[buf][warp * 64 + lane] * us[lane] * ks[buf][warp * 64 + lane]
                    + rs[buf][warp * 64 + 32 + lane] * us[32 + lane] * ks[buf][warp * 64 + 32 + lane];
#pragma unroll
            for (int o = 16; o; o >>= 1) p += __shfl_xor_sync(0xffffffffu, p, o);
            if (lane == 0) ruks[warp] = p;
        }
        __syncthreads();
        if (ci + 1 < TDIM / 8) {
            int nb = buf ^ 1;
            wkv_issue(ci + 1, rs[nb], ks[nb], vs[nb], ws[nb], rp, kp, vp, wp_, base, tid);
        }
#pragma unroll 1
        for (int tc = 0; tc < 8; tc++) {
            float vi = vs[buf][tc * 64 + i];
            const float4* r4 = (const float4*)&rs[buf][tc * 64 + jq * 16];
            const float4* k4 = (const float4*)&ks[buf][tc * 64 + jq * 16];
            const float4* w4 = (const float4*)&ws[buf][tc * 64 + jq * 16];
            float yps = 0.f;
#pragma unroll
            for (int q = 0; q < 4; q++) {
                float4 rv = r4[q], kv = k4[q], wv = w4[q];
                yps += rv.x * S[q * 4 + 0]; S[q * 4 + 0] = wv.x * S[q * 4 + 0] + kv.x * vi;
                yps += rv.y * S[q * 4 + 1]; S[q * 4 + 1] = wv.y * S[q * 4 + 1] + kv.y * vi;
                yps += rv.z * S[q * 4 + 2]; S[q * 4 + 2] = wv.z * S[q * 4 + 2] + kv.z * vi;
                yps += rv.w * S[q * 4 + 3]; S[q * 4 + 3] = wv.w * S[q * 4 + 3] + kv.w * vi;
            }
            yps += __shfl_xor_sync(0xffffffffu, yps, 1);
            yps += __shfl_xor_sync(0xffffffffu, yps, 2);
            if (jq == 0)
                yp[base + (size_t)(ci * 8 + tc) * CDIM + i] = yps + vi * ruks[tc];
        }
    }
}

// ---------------- K5: per-head GroupNorm * g ----------------
__global__ void gn_mul_kernel(const float* __restrict__ y,
                              const float* __restrict__ lw, const float* __restrict__ lb,
                              const float* __restrict__ g, float* __restrict__ out)
{
    int row = blockIdx.x;
    int warp = threadIdx.x >> 5, lane = threadIdx.x & 31;
    size_t o = (size_t)row * CDIM + warp * HS;
    float v0 = y[o + lane], v1 = y[o + 32 + lane];
    float s = v0 + v1, ss = v0 * v0 + v1 * v1;
#pragma unroll
    for (int off = 16; off; off >>= 1) {
        s  += __shfl_xor_sync(0xffffffffu, s,  off);
        ss += __shfl_xor_sync(0xffffffffu, ss, off);
    }
    float mean = s * (1.f / HS);
    float var  = ss * (1.f / HS) - mean * mean;
    float inv  = rsqrtf(var + 1e-5f);
    int c0 = warp * HS + lane, c1 = c0 + 32;
    float n0 = (v0 - mean) * inv * lw[c0] + lb[c0];
    float n1 = (v1 - mean) * inv * lw[c1] + lb[c1];
    out[o + lane]      = tf32r(n0 * g[o + lane]);
    out[o + 32 + lane] = tf32r(n1 * g[o + 32 + lane]);
}

// ---------------- launcher ----------------
extern "C" void kernel_launch(void* const* d_in, const int* in_sizes, int n_in,
                              void* d_out, int out_size)
{
    const float* x          = (const float*)d_in[0];
    const float* W_r        = (const float*)d_in[1];
    const float* W_k        = (const float*)d_in[2];
    const float* W_v        = (const float*)d_in[3];
    const float* W_g        = (const float*)d_in[4];
    const float* W_o        = (const float*)d_in[5];
    const float* maa_x      = (const float*)d_in[6];
    const float* maa_w      = (const float*)d_in[7];
    const float* maa_k      = (const float*)d_in[8];
    const float* maa_v      = (const float*)d_in[9];
    const float* maa_r      = (const float*)d_in[10];
    const float* maa_g      = (const float*)d_in[11];
    const float* maa_w1     = (const float*)d_in[12];
    const float* maa_w2     = (const float*)d_in[13];
    const float* time_decay = (const float*)d_in[14];
    const float* dec_w1     = (const float*)d_in[15];
    const float* dec_w2     = (const float*)d_in[16];
    const float* faaaa      = (const float*)d_in[17];
    const float* ln_w       = (const float*)d_in[18];
    const float* ln_b       = (const float*)d_in[19];
    float* out = (float*)d_out;

    float *xx, *xxx, *tb, *xw, *xk, *xv, *xr, *xg, *rb, *kb, *vb, *gb, *h1, *wb, *yb, *yg, *Wc, *Wt, *Wm;
    cudaGetSymbolAddress((void**)&xx,  g_xx);
    cudaGetSymbolAddress((void**)&xxx, g_xxx);
    cudaGetSymbolAddress((void**)&tb,  g_t);
    cudaGetSymbolAddress((void**)&xw,  g_xw);
    cudaGetSymbolAddress((void**)&xk,  g_xk);
    cudaGetSymbolAddress((void**)&xv,  g_xv);
    cudaGetSymbolAddress((void**)&xr,  g_xr);
    cudaGetSymbolAddress((void**)&xg,  g_xg);
    cudaGetSymbolAddress((void**)&rb,  g_r);
    cudaGetSymbolAddress((void**)&kb,  g_k);
    cudaGetSymbolAddress((void**)&vb,  g_v);
    cudaGetSymbolAddress((void**)&gb,  g_g);
    cudaGetSymbolAddress((void**)&h1,  g_h1);
    cudaGetSymbolAddress((void**)&wb,  g_w);
    cudaGetSymbolAddress((void**)&yb,  g_y);
    cudaGetSymbolAddress((void**)&yg,  g_yg);
    cudaGetSymbolAddress((void**)&Wc,  g_Wc);
    cudaGetSymbolAddress((void**)&Wt,  g_Wt);
    cudaGetSymbolAddress((void**)&Wm,  g_Wm);

    const int NW = CDIM * CDIM;
    float* Wr_c = Wc + 0 * NW;
    float* Wk_c = Wc + 1 * NW;
    float* Wv_c = Wc + 2 * NW;
    float* Wg_c = Wc + 3 * NW;
    float* Wo_c = Wc + 4 * NW;
    float* W1t  = Wt;
    float* D1t  = Wt + 160 * CDIM;
    float* D2t  = Wt + 160 * CDIM + 64 * CDIM;

    cudaFuncSetAttribute(gemm_tf32_kernel<0>, cudaFuncAttributeMaxDynamicSharedMemorySize, GT_SMEM);
    cudaFuncSetAttribute(gemm_tf32_kernel<3>, cudaFuncAttributeMaxDynamicSharedMemorySize, GT_SMEM);
    cudaFuncSetAttribute(gemm_tf32_kernel<4>, cudaFuncAttributeMaxDynamicSharedMemorySize, GT_SMEM);
    cudaFuncSetAttribute(gemm_tf32_qkvg_kernel, cudaFuncAttributeMaxDynamicSharedMemorySize, GT_SMEM);
    cudaFuncSetAttribute(mix5g_kernel, cudaFuncAttributeMaxDynamicSharedMemorySize, GT_SMEM);

    int total = NR * CDIM;

    // Launch order: slot 6 (ncu -s 5 -c 1) = mix5g_kernel.
    transpose_round_kernel<<<(CDIM * 160 + 255) / 256, 256>>>(maa_w1, W1t, CDIM, 160);   // 1
    shift_mix_kernel<<<(total + 255) / 256, 256>>>(x, maa_x, xx, xxx, total);            // 2
    {                                                                                     // 3
        dim3 grid(2, NR / 128);
        gemm_tf32_kernel<4><<<grid, 256, GT_SMEM>>>(xxx, W1t, tb, 160, CDIM, nullptr);
    }
    mixw2_prep_kernel<<<(5 * CDIM * 32 + 255) / 256, 256>>>(maa_w2, Wm);                 // 4
    round_w_kernel<<<(5 * NW + 255) / 256, 256>>>(W_r, W_k, W_v, W_g, W_o, Wc);          // 5
    {                                                                                     // 6 <- profiled
        dim3 grid(CDIM / 128, NR / 128);
        mix5g_kernel<<<grid, 256, GT_SMEM>>>(tb, Wm, x, xx,
            maa_w, maa_k, maa_v, maa_r, maa_g, xw, xk, xv, xr, xg);
    }
    {                                                                                     // 7
        dim3 grid(6, NR / 128, 4);
        gemm_tf32_qkvg_kernel<<<grid, 256, GT_SMEM>>>(
            xr, xk, xv, xg, Wr_c, Wk_c, Wv_c, Wg_c, rb, kb, vb, gb);
    }
    transpose_round_kernel<<<(CDIM * 64 + 255) / 256, 256>>>(dec_w1, D1t, CDIM, 64);
    transpose_round_kernel<<<(64 * CDIM + 255) / 256, 256>>>(dec_w2, D2t, 64, CDIM);
    {
        dim3 grid(1, NR / 128);
        gemm_tf32_kernel<4><<<grid, 256, GT_SMEM>>>(xw, D1t, h1, 64, CDIM, nullptr);
    }
    {
        dim3 gcc(6, NR / 128);
        gemm_tf32_kernel<3><<<gcc, 256, GT_SMEM>>>(h1, D2t, wb, CDIM, 64, time_decay);
    }
    wkv6_kernel<<<8 * NHEAD, 256>>>(rb, kb, vb, wb, faaaa, yb);
    gn_mul_kernel<<<NR, 384>>>(yb, ln_w, ln_b, gb, yg);
    {
        dim3 gcc(6, NR / 128);
        gemm_tf32_kernel<0><<<gcc, 256, GT_SMEM>>>(yg, Wo_c, out, CDIM, CDIM, nullptr);
    }
}

// round 10
// speedup vs baseline: 1.3316x; 1.0367x over previous
#include <cuda_runtime.h>
#include <math.h>

#define TDIM 1024
#define CDIM 768
#define PH 32
#define PW 32
#define NHEAD 12
#define HS 64
#define NR (8*1024)

__device__ float g_xx [NR*CDIM];
__device__ float g_xxx[NR*CDIM];
__device__ float g_t  [NR*160];
__device__ float g_xw [NR*CDIM];
__device__ float g_xk [NR*CDIM];
__device__ float g_xv [NR*CDIM];
__device__ float g_xr [NR*CDIM];
__device__ float g_xg [NR*CDIM];
__device__ float g_r  [NR*CDIM];
__device__ float g_k  [NR*CDIM];
__device__ float g_v  [NR*CDIM];
__device__ float g_g  [NR*CDIM];
__device__ float g_h1 [NR*64];
__device__ float g_w  [NR*CDIM];
__device__ float g_y  [NR*CDIM];
__device__ float g_yg [NR*CDIM];
__device__ float g_Wc [5*CDIM*CDIM];
__device__ float g_Wt [160*CDIM + 64*CDIM + CDIM*64];
__device__ float g_Wm [5*CDIM*32];

__device__ __forceinline__ float tf32r(float x) {
    unsigned u;
    asm("cvt.rna.tf32.f32 %0, %1;" : "=r"(u) : "f"(x));
    return __uint_as_float(u);
}
__device__ __forceinline__ void cp16(void* dst, const void* src) {
    unsigned d = (unsigned)__cvta_generic_to_shared(dst);
    asm volatile("cp.async.cg.shared.global [%0], [%1], 16;" :: "r"(d), "l"(src) : "memory");
}
__device__ __forceinline__ void cp16z(void* dst, const void* src, int sz) {
    unsigned d = (unsigned)__cvta_generic_to_shared(dst);
    asm volatile("cp.async.cg.shared.global [%0], [%1], 16, %2;" :: "r"(d), "l"(src), "r"(sz) : "memory");
}

// ---------------- fused weight prep ----------------
// ranges: [0, 5NW) Wc | [.., +160*CDIM) W1t | [.., +64*CDIM) D1t | [.., +CDIM*64) D2t | [.., +5*CDIM*32) Wm
#define NW_ (CDIM*CDIM)
#define PRE0 (5*NW_)
#define PRE1 (PRE0 + 160*CDIM)
#define PRE2 (PRE1 + 64*CDIM)
#define PRE3 (PRE2 + CDIM*64)
#define PRE4 (PRE3 + 5*CDIM*32)
__global__ void prep_all_kernel(const float* __restrict__ w0, const float* __restrict__ w1,
                                const float* __restrict__ w2, const float* __restrict__ w3,
                                const float* __restrict__ w4,
                                const float* __restrict__ maa_w1, const float* __restrict__ dec_w1,
                                const float* __restrict__ dec_w2, const float* __restrict__ maa_w2,
                                float* __restrict__ Wc, float* __restrict__ Wt, float* __restrict__ Wm)
{
    int idx = blockIdx.x * blockDim.x + threadIdx.x;
    if (idx >= PRE4) return;
    if (idx < PRE0) {
        int m = idx / NW_, r = idx % NW_;
        const float* src = (m == 0) ? w0 : (m == 1) ? w1 : (m == 2) ? w2 : (m == 3) ? w3 : w4;
        Wc[idx] = tf32r(src[r]);
    } else if (idx < PRE1) {
        int o = idx - PRE0;
        int n = o / CDIM, k = o % CDIM;
        Wt[o] = tf32r(maa_w1[k * 160 + n]);
    } else if (idx < PRE2) {
        int o = idx - PRE1;
        int n = o / CDIM, k = o % CDIM;
        Wt[160 * CDIM + o] = tf32r(dec_w1[k * 64 + n]);
    } else if (idx < PRE3) {
        int o = idx - PRE2;
        int n = o / 64, k = o % 64;
        Wt[160 * CDIM + 64 * CDIM + o] = tf32r(dec_w2[k * CDIM + n]);
    } else {
        int o = idx - PRE3;
        int f = o / (CDIM * 32);
        int rem = o % (CDIM * 32);
        int c = rem >> 5, j = rem & 31;
        Wm[o] = tf32r(maa_w2[(f * 32 + j) * CDIM + c]);
    }
}

// ---------------- K1: q_shift + maa_x mix (float4) ----------------
#define C4 (CDIM/4)
__global__ void shift_mix_kernel(const float* __restrict__ x,
                                 const float* __restrict__ maa_x,
                                 float* __restrict__ xx, float* __restrict__ xxx,
                                 int total4)
{
    int idx = blockIdx.x * blockDim.x + threadIdx.x;
    if (idx >= total4) return;
    int c4 = idx % C4;
    int t = (idx / C4) % TDIM;
    int b = idx / (C4 * TDIM);
    int d4 = c4 & 15;                   // 16 float4 per head
    int hh = t >> 5, ww = t & 31;
    int st = -1;
    if (d4 < 4)       { if (ww >= 1)      st = t - 1;  }
    else if (d4 < 8)  { if (ww < PW - 1)  st = t + 1;  }
    else if (d4 < 12) { if (hh >= 1)      st = t - PW; }
    else              { if (hh < PH - 1)  st = t + PW; }
    float4 sh = make_float4(0.f, 0.f, 0.f, 0.f);
    if (st >= 0)
        sh = *(const float4*)(x + (((size_t)b * TDIM + st) * C4 + c4) * 4);
    float4 xv = *(const float4*)(x + (size_t)idx * 4);
    float4 mm = *(const float4*)(maa_x + c4 * 4);
    float4 dd, ox;
    dd.x = sh.x - xv.x; dd.y = sh.y - xv.y; dd.z = sh.z - xv.z; dd.w = sh.w - xv.w;
    ox.x = tf32r(xv.x + dd.x * mm.x);
    ox.y = tf32r(xv.y + dd.y * mm.y);
    ox.z = tf32r(xv.z + dd.z * mm.z);
    ox.w = tf32r(xv.w + dd.w * mm.w);
    *(float4*)(xx + (size_t)idx * 4) = dd;
    *(float4*)(xxx + (size_t)idx * 4) = ox;
}

// ---------------- mma.sync tf32 GEMM ----------------
#define ASTR   36
#define ASZ    (128*ASTR)
#define GT_SMEM (4*ASZ*4)

template<int EPI>
__device__ __forceinline__ float epi_f(float a, const float* bias, int n) {
    if (EPI == 1) return tanhf(a);
    if (EPI == 2) return fmaxf(a, 0.f);
    if (EPI == 3) return a + bias[n];
    if (EPI == 4) return tf32r(tanhf(a));
    return a;
}

__device__ __forceinline__ void gt_issue(float* sm, const float* __restrict__ A,
                                         const float* __restrict__ Bm,
                                         int m0, int n0, int it, int tid, int N, int K)
{
    int s = it & 1;
    float* As = sm + s * ASZ;
    float* Bs = sm + 2 * ASZ + s * ASZ;
    int k0 = it * 32;
#pragma unroll
    for (int p = 0; p < 4; p++) {
        int c = tid + p * 256;
        int row = c >> 3, kc = (c & 7) << 2;
        cp16(As + row * ASTR + kc, A + (size_t)(m0 + row) * K + k0 + kc);
    }
#pragma unroll
    for (int p = 0; p < 4; p++) {
        int c = tid + p * 256;
        int row = c >> 3, kc = (c & 7) << 2;
        int valid = (n0 + row) < N;
        const float* src = Bm + (valid ? ((size_t)(n0 + row) * K + k0 + kc) : 0);
        cp16z(Bs + row * ASTR + kc, src, valid ? 16 : 0);
    }
    asm volatile("cp.async.commit_group;" ::: "memory");
}

// fragment compute for one 32-K stage buffer
__device__ __forceinline__ void gt_mma_stage(const float* As, const float* Bs,
                                             int warp_m, int warp_n, int lane,
                                             float acc[4][4][4])
{
    int lrow = lane & 7;
    int a_m = ((lane >> 3) & 1) * 8 + lrow;
    int a_k = (lane >> 4) * 4;
    int b_row8 = ((lane >> 4) & 1) * 8 + lrow;     // row offset within ni-pair
    int b_k = ((lane >> 3) & 1) * 4;
#pragma unroll
    for (int ks = 0; ks < 4; ks++) {
        unsigned af[4][4], bf[4][2];
#pragma unroll
        for (int mi = 0; mi < 4; mi++) {
            const float* p = As + (warp_m * 64 + mi * 16 + a_m) * ASTR + ks * 8 + a_k;
            unsigned ad = (unsigned)__cvta_generic_to_shared(p);
            asm volatile("ldmatrix.sync.aligned.m8n8.x4.shared.b16 {%0,%1,%2,%3}, [%4];"
                : "=r"(af[mi][0]), "=r"(af[mi][1]), "=r"(af[mi][2]), "=r"(af[mi][3]) : "r"(ad));
        }
#pragma unroll
        for (int np = 0; np < 2; np++) {
            const float* p = Bs + (warp_n * 32 + np * 16 + b_row8) * ASTR + ks * 8 + b_k;
            unsigned ad = (unsigned)__cvta_generic_to_shared(p);
            asm volatile("ldmatrix.sync.aligned.m8n8.x4.shared.b16 {%0,%1,%2,%3}, [%4];"
                : "=r"(bf[np * 2][0]), "=r"(bf[np * 2][1]),
                  "=r"(bf[np * 2 + 1][0]), "=r"(bf[np * 2 + 1][1]) : "r"(ad));
        }
#pragma unroll
        for (int mi = 0; mi < 4; mi++)
#pragma unroll
            for (int ni = 0; ni < 4; ni++) {
                asm volatile(
                    "mma.sync.aligned.m16n8k8.row.col.f32.tf32.tf32.f32 "
                    "{%0,%1,%2,%3}, {%4,%5,%6,%7}, {%8,%9}, {%0,%1,%2,%3};"
                    : "+f"(acc[mi][ni][0]), "+f"(acc[mi][ni][1]),
                      "+f"(acc[mi][ni][2]), "+f"(acc[mi][ni][3])
                    : "r"(af[mi][0]), "r"(af[mi][1]), "r"(af[mi][2]), "r"(af[mi][3]),
                      "r"(bf[ni][0]), "r"(bf[ni][1]));
            }
    }
}

template<int EPI, bool RELU_RT>
__device__ __forceinline__ void gt_body(const float* __restrict__ A, const float* __restrict__ Bm,
                                        float* __restrict__ Cm, int N, int K,
                                        const float* __restrict__ bias, int relu_flag)
{
    extern __shared__ __align__(16) float sm[];
    int tid = threadIdx.x;
    int lane = tid & 31, warp = tid >> 5;
    int warp_m = warp >> 2, warp_n = warp & 3;
    int m0 = blockIdx.y * 128, n0 = blockIdx.x * 128;

    float acc[4][4][4];
#pragma unroll
    for (int i = 0; i < 4; i++)
#pragma unroll
        for (int j = 0; j < 4; j++)
#pragma unroll
            for (int q = 0; q < 4; q++) acc[i][j][q] = 0.f;

    gt_issue(sm, A, Bm, m0, n0, 0, tid, N, K);

    const int NIT = K / 32;
#pragma unroll 1
    for (int it = 0; it < NIT; it++) {
        if (it + 1 < NIT) {
            gt_issue(sm, A, Bm, m0, n0, it + 1, tid, N, K);
            asm volatile("cp.async.wait_group 1;" ::: "memory");
        } else {
            asm volatile("cp.async.wait_group 0;" ::: "memory");
        }
        __syncthreads();
        int s = it & 1;
        gt_mma_stage(sm + s * ASZ, sm + 2 * ASZ + s * ASZ, warp_m, warp_n, lane, acc);
        __syncthreads();
    }

    int erow = lane >> 2, ecol = (lane & 3) * 2;
#pragma unroll
    for (int mi = 0; mi < 4; mi++) {
#pragma unroll
        for (int ni = 0; ni < 4; ni++) {
            int m = m0 + warp_m * 64 + mi * 16 + erow;
            int n = n0 + warp_n * 32 + ni * 8 + ecol;
            if (n < N) {
                float2 v0, v1;
                v0.x = epi_f<EPI>(acc[mi][ni][0], bias, n);
                v0.y = epi_f<EPI>(acc[mi][ni][1], bias, n + 1);
                v1.x = epi_f<EPI>(acc[mi][ni][2], bias, n);
                v1.y = epi_f<EPI>(acc[mi][ni][3], bias, n + 1);
                if (RELU_RT && relu_flag) {
                    v0.x = fmaxf(v0.x, 0.f); v0.y = fmaxf(v0.y, 0.f);
                    v1.x = fmaxf(v1.x, 0.f); v1.y = fmaxf(v1.y, 0.f);
                }
                *(float2*)(Cm + (size_t)m * N + n) = v0;
                *(float2*)(Cm + (size_t)(m + 8) * N + n) = v1;
            }
        }
    }
}

template<int EPI>
__global__ __launch_bounds__(256, 2) void gemm_tf32_kernel(
    const float* __restrict__ A, const float* __restrict__ Bm,
    float* __restrict__ Cm, int N, int K, const float* __restrict__ bias)
{
    gt_body<EPI, false>(A, Bm, Cm, N, K, bias, 0);
}

// batched over z: r,k,v,g (K=768) + w-decay (K=64, +bias)
__global__ __launch_bounds__(256, 2) void gemm_tf32_batch5_kernel(
    const float* __restrict__ a0, const float* __restrict__ a1,
    const float* __restrict__ a2, const float* __restrict__ a3,
    const float* __restrict__ a4,
    const float* __restrict__ b0, const float* __restrict__ b1,
    const float* __restrict__ b2, const float* __restrict__ b3,
    const float* __restrict__ b4,
    float* __restrict__ c0, float* __restrict__ c1,
    float* __restrict__ c2, float* __restrict__ c3,
    float* __restrict__ c4,
    const float* __restrict__ bias4)
{
    int z = blockIdx.z;
    if (z < 4) {
        const float* A  = (z == 0) ? a0 : (z == 1) ? a1 : (z == 2) ? a2 : a3;
        const float* Bm = (z == 0) ? b0 : (z == 1) ? b1 : (z == 2) ? b2 : b3;
        float* Cm       = (z == 0) ? c0 : (z == 1) ? c1 : (z == 2) ? c2 : c3;
        gt_body<0, true>(A, Bm, Cm, CDIM, CDIM, nullptr, z == 3);
    } else {
        gt_body<3, false>(a4, b4, c4, CDIM, 64, bias4, 0);
    }
}

// ---------------- mix5 as GEMM with fused combine epilogue ----------------
__device__ __forceinline__ void m5_issue(float* sm, const float* __restrict__ tb,
                                         const float* __restrict__ Wm,
                                         int m0, int n0, int f, int tid)
{
    int s = f & 1;
    float* As = sm + s * ASZ;
    float* Bs = sm + 2 * ASZ + s * ASZ;
#pragma unroll
    for (int p = 0; p < 4; p++) {
        int c = tid + p * 256;
        int row = c >> 3, kc = (c & 7) << 2;
        cp16(As + row * ASTR + kc, tb + (size_t)(m0 + row) * 160 + f * 32 + kc);
        cp16(Bs + row * ASTR + kc, Wm + (size_t)f * CDIM * 32 + (size_t)(n0 + row) * 32 + kc);
    }
    asm volatile("cp.async.commit_group;" ::: "memory");
}

__global__ __launch_bounds__(256, 2) void mix5g_kernel(
    const float* __restrict__ tb, const float* __restrict__ Wm,
    const float* __restrict__ x, const float* __restrict__ xx,
    const float* __restrict__ mw, const float* __restrict__ mk,
    const float* __restrict__ mv, const float* __restrict__ mr,
    const float* __restrict__ mg,
    float* __restrict__ xw, float* __restrict__ xk, float* __restrict__ xv,
    float* __restrict__ xr, float* __restrict__ xg)
{
    extern __shared__ __align__(16) float sm[];
    int tid = threadIdx.x;
    int lane = tid & 31, warp = tid >> 5;
    int warp_m = warp >> 2, warp_n = warp & 3;
    int m0 = blockIdx.y * 128, n0 = blockIdx.x * 128;
    int erow = lane >> 2, ecol = (lane & 3) * 2;

    m5_issue(sm, tb, Wm, m0, n0, 0, tid);

#pragma unroll 1
    for (int f = 0; f < 5; f++) {
        if (f + 1 < 5) {
            m5_issue(sm, tb, Wm, m0, n0, f + 1, tid);
            asm volatile("cp.async.wait_group 1;" ::: "memory");
        } else {
            asm volatile("cp.async.wait_group 0;" ::: "memory");
        }
        __syncthreads();

        float acc[4][4][4];
#pragma unroll
        for (int i = 0; i < 4; i++)
#pragma unroll
            for (int j = 0; j < 4; j++)
#pragma unroll
                for (int q = 0; q < 4; q++) acc[i][j][q] = 0.f;

        int s = f & 1;
        gt_mma_stage(sm + s * ASZ, sm + 2 * ASZ + s * ASZ, warp_m, warp_n, lane, acc);
        __syncthreads();

        const float* maa_f = (f == 0) ? mw : (f == 1) ? mk : (f == 2) ? mv : (f == 3) ? mr : mg;
        float* out_f       = (f == 0) ? xw : (f == 1) ? xk : (f == 2) ? xv : (f == 3) ? xr : xg;
#pragma unroll
        for (int mi = 0; mi < 4; mi++) {
#pragma unroll
            for (int ni = 0; ni < 4; ni++) {
                int m = m0 + warp_m * 64 + mi * 16 + erow;
                int n = n0 + warp_n * 32 + ni * 8 + ecol;
                size_t gi0 = (size_t)m * CDIM + n;
                size_t gi1 = (size_t)(m + 8) * CDIM + n;
                float2 xa = *(const float2*)(x + gi0);
                float2 xb = *(const float2*)(x + gi1);
                float2 da = *(const float2*)(xx + gi0);
                float2 db = *(const float2*)(xx + gi1);
                float2 ma = *(const float2*)(maa_f + n);
                float2 v0, v1;
                v0.x = tf32r(xa.x + da.x * (ma.x + acc[mi][ni][0]));
                v0.y = tf32r(xa.y + da.y * (ma.y + acc[mi][ni][1]));
                v1.x = tf32r(xb.x + db.x * (ma.x + acc[mi][ni][2]));
                v1.y = tf32r(xb.y + db.y * (ma.y + acc[mi][ni][3]));
                *(float2*)(out_f + gi0) = v0;
                *(float2*)(out_f + gi1) = v1;
            }
        }
    }
}

// ---------------- K4: WKV6 recurrence ----------------
__device__ __forceinline__ void wkv_issue(int ci, float* rsb, float* ksb,
        float* vsb, float* wsb,
        const float* rp, const float* kp, const float* vp, const float* wpp,
        size_t base, int tid)
{
#pragma unroll
    for (int p = 0; p < 2; p++) {
        int idx = tid + p * 256;
        int arr = idx >> 7;
        int rem = idx & 127;
        int tc = rem >> 4, c4 = (rem & 15) << 2;
        size_t gofs = base + (size_t)(ci * 8 + tc) * CDIM + c4;
        float* dst; const float* src;
        if (arr == 0)      { dst = rsb + tc * 64 + c4; src = rp  + gofs; }
        else if (arr == 1) { dst = ksb + tc * 64 + c4; src = kp  + gofs; }
        else if (arr == 2) { dst = vsb + tc * 64 + c4; src = vp  + gofs; }
        else               { dst = wsb + tc * 64 + c4; src = wpp + gofs; }
        cp16(dst, src);
    }
    asm volatile("cp.async.commit_group;" ::: "memory");
}

__global__ __launch_bounds__(256, 1) void wkv6_kernel(
    const float* __restrict__ rp, const float* __restrict__ kp,
    const float* __restrict__ vp, const float* __restrict__ wp_,
    const float* __restrict__ up, float* __restrict__ yp)
{
    __shared__ __align__(16) float rs[2][512], ks[2][512], vs[2][512], ws[2][512];
    __shared__ float us[64], ruks[8];
    int tid = threadIdx.x;
    int b = blockIdx.x / NHEAD, h = blockIdx.x % NHEAD;
    size_t base = (size_t)b * TDIM * CDIM + h * HS;
    if (tid < 64) us[tid] = up[h * HS + tid];
    int i = tid >> 2, jq = tid & 3;
    int lane = tid & 31, warp = tid >> 5;

    float S[16];
#pragma unroll
    for (int q = 0; q < 16; q++) S[q] = 0.f;

    wkv_issue(0, rs[0], ks[0], vs[0], ws[0], rp, kp, vp, wp_, base, tid);

#pragma unroll 1
    for (int ci = 0; ci < TDIM / 8; ci++) {
        int buf = ci & 1;
        asm volatile("cp.async.wait_group 0;" ::: "memory");
        __syncthreads();
        for (int idx = tid; idx < 512; idx += 256)
            ws[buf][idx] = expf(-expf(ws[buf][idx]));
        {
            float p = rs[buf][warp * 64 + lane] * us[lane] * ks[buf][warp * 64 + lane]
                    + rs[buf][warp * 64 + 32 + lane] * us[32 + lane] * ks[buf][warp * 64 + 32 + lane];
#pragma unroll
            for (int o = 16; o; o >>= 1) p += __shfl_xor_sync(0xffffffffu, p, o);
            if (lane == 0) ruks[warp] = p;
        }
        __syncthreads();
        if (ci + 1 < TDIM / 8) {
            int nb = buf ^ 1;
            wkv_issue(ci + 1, rs[nb], ks[nb], vs[nb], ws[nb], rp, kp, vp, wp_, base, tid);
        }
#pragma unroll 1
        for (int tc = 0; tc < 8; tc++) {
            float vi = vs[buf][tc * 64 + i];
            const float4* r4 = (const float4*)&rs[buf][tc * 64 + jq * 16];
            const float4* k4 = (const float4*)&ks[buf][tc * 64 + jq * 16];
            const float4* w4 = (const float4*)&ws[buf][tc * 64 + jq * 16];
            float yps = 0.f;
#pragma unroll
            for (int q = 0; q < 4; q++) {
                float4 rv = r4[q], kv = k4[q], wv = w4[q];
                yps += rv.x * S[q * 4 + 0]; S[q * 4 + 0] = wv.x * S[q * 4 + 0] + kv.x * vi;
                yps += rv.y * S[q * 4 + 1]; S[q * 4 + 1] = wv.y * S[q * 4 + 1] + kv.y * vi;
                yps += rv.z * S[q * 4 + 2]; S[q * 4 + 2] = wv.z * S[q * 4 + 2] + kv.z * vi;
                yps += rv.w * S[q * 4 + 3]; S[q * 4 + 3] = wv.w * S[q * 4 + 3] + kv.w * vi;
            }
            yps += __shfl_xor_sync(0xffffffffu, yps, 1);
            yps += __shfl_xor_sync(0xffffffffu, yps, 2);
            if (jq == 0)
                yp[base + (size_t)(ci * 8 + tc) * CDIM + i] = yps + vi * ruks[tc];
        }
    }
}

// ---------------- K5: per-head GroupNorm * g ----------------
__global__ void gn_mul_kernel(const float* __restrict__ y,
                              const float* __restrict__ lw, const float* __restrict__ lb,
                              const float* __restrict__ g, float* __restrict__ out)
{
    int row = blockIdx.x;
    int warp = threadIdx.x >> 5, lane = threadIdx.x & 31;
    size_t o = (size_t)row * CDIM + warp * HS;
    float v0 = y[o + lane], v1 = y[o + 32 + lane];
    float s = v0 + v1, ss = v0 * v0 + v1 * v1;
#pragma unroll
    for (int off = 16; off; off >>= 1) {
        s  += __shfl_xor_sync(0xffffffffu, s,  off);
        ss += __shfl_xor_sync(0xffffffffu, ss, off);
    }
    float mean = s * (1.f / HS);
    float var  = ss * (1.f / HS) - mean * mean;
    float inv  = rsqrtf(var + 1e-5f);
    int c0 = warp * HS + lane, c1 = c0 + 32;
    float n0 = (v0 - mean) * inv * lw[c0] + lb[c0];
    float n1 = (v1 - mean) * inv * lw[c1] + lb[c1];
    out[o + lane]      = tf32r(n0 * g[o + lane]);
    out[o + 32 + lane] = tf32r(n1 * g[o + 32 + lane]);
}

// ---------------- launcher ----------------
extern "C" void kernel_launch(void* const* d_in, const int* in_sizes, int n_in,
                              void* d_out, int out_size)
{
    const float* x          = (const float*)d_in[0];
    const float* W_r        = (const float*)d_in[1];
    const float* W_k        = (const float*)d_in[2];
    const float* W_v        = (const float*)d_in[3];
    const float* W_g        = (const float*)d_in[4];
    const float* W_o        = (const float*)d_in[5];
    const float* maa_x      = (const float*)d_in[6];
    const float* maa_w      = (const float*)d_in[7];
    const float* maa_k      = (const float*)d_in[8];
    const float* maa_v      = (const float*)d_in[9];
    const float* maa_r      = (const float*)d_in[10];
    const float* maa_g      = (const float*)d_in[11];
    const float* maa_w1     = (const float*)d_in[12];
    const float* maa_w2     = (const float*)d_in[13];
    const float* time_decay = (const float*)d_in[14];
    const float* dec_w1     = (const float*)d_in[15];
    const float* dec_w2     = (const float*)d_in[16];
    const float* faaaa      = (const float*)d_in[17];
    const float* ln_w       = (const float*)d_in[18];
    const float* ln_b       = (const float*)d_in[19];
    float* out = (float*)d_out;

    float *xx, *xxx, *tb, *xw, *xk, *xv, *xr, *xg, *rb, *kb, *vb, *gb, *h1, *wb, *yb, *yg, *Wc, *Wt, *Wm;
    cudaGetSymbolAddress((void**)&xx,  g_xx);
    cudaGetSymbolAddress((void**)&xxx, g_xxx);
    cudaGetSymbolAddress((void**)&tb,  g_t);
    cudaGetSymbolAddress((void**)&xw,  g_xw);
    cudaGetSymbolAddress((void**)&xk,  g_xk);
    cudaGetSymbolAddress((void**)&xv,  g_xv);
    cudaGetSymbolAddress((void**)&xr,  g_xr);
    cudaGetSymbolAddress((void**)&xg,  g_xg);
    cudaGetSymbolAddress((void**)&rb,  g_r);
    cudaGetSymbolAddress((void**)&kb,  g_k);
    cudaGetSymbolAddress((void**)&vb,  g_v);
    cudaGetSymbolAddress((void**)&gb,  g_g);
    cudaGetSymbolAddress((void**)&h1,  g_h1);
    cudaGetSymbolAddress((void**)&wb,  g_w);
    cudaGetSymbolAddress((void**)&yb,  g_y);
    cudaGetSymbolAddress((void**)&yg,  g_yg);
    cudaGetSymbolAddress((void**)&Wc,  g_Wc);
    cudaGetSymbolAddress((void**)&Wt,  g_Wt);
    cudaGetSymbolAddress((void**)&Wm,  g_Wm);

    const int NW = CDIM * CDIM;
    float* Wr_c = Wc + 0 * NW;
    float* Wk_c = Wc + 1 * NW;
    float* Wv_c = Wc + 2 * NW;
    float* Wg_c = Wc + 3 * NW;
    float* Wo_c = Wc + 4 * NW;
    float* W1t  = Wt;
    float* D1t  = Wt + 160 * CDIM;
    float* D2t  = Wt + 160 * CDIM + 64 * CDIM;

    cudaFuncSetAttribute(gemm_tf32_kernel<0>, cudaFuncAttributeMaxDynamicSharedMemorySize, GT_SMEM);
    cudaFuncSetAttribute(gemm_tf32_kernel<4>, cudaFuncAttributeMaxDynamicSharedMemorySize, GT_SMEM);
    cudaFuncSetAttribute(gemm_tf32_batch5_kernel, cudaFuncAttributeMaxDynamicSharedMemorySize, GT_SMEM);
    cudaFuncSetAttribute(mix5g_kernel, cudaFuncAttributeMaxDynamicSharedMemorySize, GT_SMEM);

    int total4 = NR * C4;

    prep_all_kernel<<<(PRE4 + 255) / 256, 256>>>(W_r, W_k, W_v, W_g, W_o,            // 1
        maa_w1, dec_w1, dec_w2, maa_w2, Wc, Wt, Wm);
    shift_mix_kernel<<<(total4 + 255) / 256, 256>>>(x, maa_x, xx, xxx, total4);      // 2
    {                                                                                 // 3
        dim3 grid(2, NR / 128);
        gemm_tf32_kernel<4><<<grid, 256, GT_SMEM>>>(xxx, W1t, tb, 160, CDIM, nullptr);
    }
    {                                                                                 // 4 <- profiled
        dim3 grid(CDIM / 128, NR / 128);
        mix5g_kernel<<<grid, 256, GT_SMEM>>>(tb, Wm, x, xx,
            maa_w, maa_k, maa_v, maa_r, maa_g, xw, xk, xv, xr, xg);
    }
    {                                                                                 // 5
        dim3 grid(1, NR / 128);
        gemm_tf32_kernel<4><<<grid, 256, GT_SMEM>>>(xw, D1t, h1, 64, CDIM, nullptr);
    }
    {                                                                                 // 6
        dim3 grid(6, NR / 128, 5);
        gemm_tf32_batch5_kernel<<<grid, 256, GT_SMEM>>>(
            xr, xk, xv, xg, h1, Wr_c, Wk_c, Wv_c, Wg_c, D2t,
            rb, kb, vb, gb, wb, time_decay);
    }
    wkv6_kernel<<<8 * NHEAD, 256>>>(rb, kb, vb, wb, faaaa, yb);                       // 7
    gn_mul_kernel<<<NR, 384>>>(yb, ln_w, ln_b, gb, yg);                               // 8
    {                                                                                 // 9
        dim3 gcc(6, NR / 128);
        gemm_tf32_kernel<0><<<gcc, 256, GT_SMEM>>>(yg, Wo_c, out, CDIM, CDIM, nullptr);
    }
}